// round 9
// baseline (speedup 1.0000x reference)
#include <cuda_runtime.h>
#include <math.h>
#include <stdint.h>

#define THREADS 1024
#define NWARP 32
#define M 8192            // packed complex FFT size
#define NFULL 16384       // real signal length
#define ROWS 512
#define PI_D 3.14159265358979323846

// ---------------- per-row outputs + completion counter (no allocation) --------
struct RowOut { double pear, cosv, absd, tp, nmi; };
__device__ RowOut  g_row[ROWS];
__device__ unsigned g_done = 0;    // monotonic across launches; (prev % ROWS) picks finalizer

// ---------------- complex helpers ----------------
__device__ __forceinline__ float2 cmul(float2 a, float2 b){
    return make_float2(a.x*b.x - a.y*b.y, a.x*b.y + a.y*b.x);
}
__device__ __forceinline__ float2 cadd(float2 a, float2 b){ return make_float2(a.x+b.x, a.y+b.y); }
__device__ __forceinline__ float2 csub(float2 a, float2 b){ return make_float2(a.x-b.x, a.y-b.y); }
__device__ __forceinline__ float2 cconj(float2 a){ return make_float2(a.x, -a.y); }

__device__ __forceinline__ float warp_sum(float v){
    #pragma unroll
    for (int o = 16; o; o >>= 1) v += __shfl_down_sync(0xffffffffu, v, o);
    return v;
}
__device__ __forceinline__ double warp_sum_d(double v){
    #pragma unroll
    for (int o = 16; o; o >>= 1) v += __shfl_down_sync(0xffffffffu, v, o);
    return v;
}

// e^{-i pi f} (forward) / e^{+i pi f} (inverse)
template<int INV>
__device__ __forceinline__ float2 eip(float f){
    float s, c;
    sincospif(INV ? f : -f, &s, &c);
    return make_float2(c, s);
}

template<int INV>
__device__ __forceinline__ float2 cmulK(float2 a, float wr, float wi){
    float i2 = INV ? -wi : wi;
    return make_float2(a.x*wr - a.y*i2, a.x*i2 + a.y*wr);
}

// radix-4 DIT butterfly (natural-order DFT4)
template<int INV>
__device__ __forceinline__ void bfly4(float2 b0, float2 b1, float2 b2, float2 b3,
                                      float2& o0, float2& o1, float2& o2, float2& o3){
    float2 s  = cadd(b0, b2), d  = csub(b0, b2);
    float2 s2 = cadd(b1, b3), d2 = csub(b1, b3);
    o0 = cadd(s, s2); o2 = csub(s, s2);
    if (!INV){ o1 = make_float2(d.x + d2.y, d.y - d2.x); o3 = make_float2(d.x - d2.y, d.y + d2.x); }
    else     { o1 = make_float2(d.x - d2.y, d.y + d2.x); o3 = make_float2(d.x + d2.y, d.y - d2.x); }
}

// 8-point FFT in registers, natural in/out
template<int INV>
__device__ __forceinline__ void fft8(float2* x){
    const float R2 = 0.7071067811865476f;
    float2 e0,e1,e2,e3, o0,o1,o2,o3;
    bfly4<INV>(x[0], x[2], x[4], x[6], e0, e1, e2, e3);
    bfly4<INV>(x[1], x[3], x[5], x[7], o0, o1, o2, o3);
    float2 t1 = cmulK<INV>(o1,  R2, -R2);                      // W8^1
    float2 t2 = INV ? make_float2(-o2.y, o2.x) : make_float2(o2.y, -o2.x);  // (+/-)i
    float2 t3 = cmulK<INV>(o3, -R2, -R2);                      // W8^3
    x[0] = cadd(e0, o0); x[4] = csub(e0, o0);
    x[1] = cadd(e1, t1); x[5] = csub(e1, t1);
    x[2] = cadd(e2, t2); x[6] = csub(e2, t2);
    x[3] = cadd(e3, t3); x[7] = csub(e3, t3);
}

// XOR swizzle for the L=8 -> L=64 intermediate buffer (kills 4-way write conflict)
__device__ __forceinline__ int swz(int a){ return a ^ (((a >> 6) & 3) << 3); }

// Stockham radix-8 pass at sub-length L = 2^LOG2L, 1024 threads, one iteration.
// out[r + L(8s + c)] = sum_m in[r + Ls + 1024 m] * W_{8L}^{rm} * W_8^{cm}
// SWW: swizzle writes (use on L=8 pass).  SWR: swizzle reads (use on L=64 pass).
template<int LOG2L, int INV, int SWR, int SWW>
__device__ __forceinline__ void pass8(const float* __restrict__ ri, const float* __restrict__ ii,
                                      float* __restrict__ ro, float* __restrict__ io){
    const int L = 1 << LOG2L;
    int j = threadIdx.x;
    int r = j & (L - 1);
    int s = j >> LOG2L;
    float2 x[8];
    #pragma unroll
    for (int m = 0; m < 8; m++){
        int a = j + 1024*m;
        if (SWR) a = swz(a);
        x[m].x = ri[a]; x[m].y = ii[a];
    }
    if (LOG2L > 0){
        // w1 = e^{-i pi r/(4L)}; powers via log-depth tree
        float2 w1 = eip<INV>((float)r * (1.0f / (4.0f * (float)L)));
        float2 w2 = cmul(w1, w1);
        float2 w3 = cmul(w1, w2);
        float2 w4 = cmul(w2, w2);
        x[1] = cmul(x[1], w1);
        x[2] = cmul(x[2], w2);
        x[3] = cmul(x[3], w3);
        x[4] = cmul(x[4], w4);
        x[5] = cmul(x[5], cmul(w2, w3));
        x[6] = cmul(x[6], cmul(w3, w3));
        x[7] = cmul(x[7], cmul(w3, w4));
    }
    fft8<INV>(x);
    int base = r + (s << (LOG2L + 3));
    #pragma unroll
    for (int c = 0; c < 8; c++){
        int a = base + (c << LOG2L);
        if (SWW) a = swz(a);
        ro[a] = x[c].x; io[a] = x[c].y;
    }
}

// final Stockham radix-2 pass (L=4096), 1024 threads, 4 iterations
template<int INV>
__device__ __forceinline__ void pass2(const float* __restrict__ ri, const float* __restrict__ ii,
                                      float* __restrict__ ro, float* __restrict__ io){
    #pragma unroll
    for (int it = 0; it < 4; it++){
        int j = threadIdx.x + it * 1024;
        float2 a = make_float2(ri[j], ii[j]);
        float2 b = make_float2(ri[j + 4096], ii[j + 4096]);
        float2 v = cmul(b, eip<INV>((float)j * (1.0f / 4096.0f)));
        ro[j] = a.x + v.x;        io[j] = a.y + v.y;
        ro[j + 4096] = a.x - v.x; io[j + 4096] = a.y - v.y;
    }
}

// unpack X[k] of the length-16384 real signal from packed spectrum planes
__device__ __forceinline__ float2 spec_at(const float* __restrict__ re, const float* __restrict__ im,
                                          int k, float2 w){
    int k1 = k & (M - 1), k2 = (M - k) & (M - 1);
    float2 a = make_float2(re[k1], im[k1]);
    float2 b = make_float2(re[k2], im[k2]);
    float2 E = make_float2(0.5f*(a.x + b.x),  0.5f*(a.y - b.y));
    float2 O = make_float2(0.5f*(a.y + b.y), -0.5f*(a.x - b.x));
    float2 WO = cmul(w, O);
    return make_float2(E.x + WO.x, E.y + WO.y);
}

// ---------------- single fused kernel: one CTA per row, last CTA finalizes ----
__global__ __launch_bounds__(THREADS, 1)
void row_kernel(const float* __restrict__ pred, const float* __restrict__ targ,
                const int* __restrict__ pi, const int* __restrict__ pep,
                float* __restrict__ out){
    extern __shared__ float smf[];
    float* Ar = smf;
    float* Ai = smf + 8192;
    float* Br = smf + 16384;
    float* Bi = smf + 24576;
    float* Cr = smf + 32768;
    float* Ci = smf + 40960;

    __shared__ float    s_red[NWARP][10];
    __shared__ int      s_idx[NWARP];
    __shared__ float    s_mm[4];
    __shared__ unsigned hist[100];
    __shared__ float    s_hx[10], s_hy[10];
    __shared__ float2   s_c8192;
    __shared__ unsigned s_last;
    __shared__ double   s_fin[NWARP][5];

    const int tid  = threadIdx.x;
    const int warp = tid >> 5, lane = tid & 31;
    const int row  = blockIdx.x;
    const int i0   = *pi;

    double r_pear = 0.0, r_cos = 0.0, r_absd = 0.0, r_tp = 0.0, r_nmi = 0.0;

    const float2* xr = (const float2*)(pred + ((size_t)i0 * ROWS + row) * (size_t)NFULL);
    const float2* yr = (const float2*)(targ + (size_t)row * (size_t)NFULL);

    if (tid < 100) hist[tid] = 0u;

    // ---- load (SoA natural order) + Pearson moments + min/max ----
    float sx = 0.f, sy = 0.f, sxy = 0.f, sx2 = 0.f, sy2 = 0.f;
    float xmn = INFINITY, xmx = -INFINITY, ymn = INFINITY, ymx = -INFINITY;
    #pragma unroll 4
    for (int it = 0; it < 8; it++){
        int n = tid + it * THREADS;
        float2 a = xr[n], b = yr[n];
        sx  += a.x + a.y;          sy  += b.x + b.y;
        sxy += a.x*b.x + a.y*b.y;
        sx2 += a.x*a.x + a.y*a.y;  sy2 += b.x*b.x + b.y*b.y;
        xmn = fminf(xmn, fminf(a.x, a.y)); xmx = fmaxf(xmx, fmaxf(a.x, a.y));
        ymn = fminf(ymn, fminf(b.x, b.y)); ymx = fmaxf(ymx, fmaxf(b.x, b.y));
        Ar[n] = a.x; Ai[n] = a.y;
        Br[n] = b.x; Bi[n] = b.y;
    }
    sx  = warp_sum(sx);  sy  = warp_sum(sy); sxy = warp_sum(sxy);
    sx2 = warp_sum(sx2); sy2 = warp_sum(sy2);
    #pragma unroll
    for (int o = 16; o; o >>= 1){
        xmn = fminf(xmn, __shfl_down_sync(0xffffffffu, xmn, o));
        xmx = fmaxf(xmx, __shfl_down_sync(0xffffffffu, xmx, o));
        ymn = fminf(ymn, __shfl_down_sync(0xffffffffu, ymn, o));
        ymx = fmaxf(ymx, __shfl_down_sync(0xffffffffu, ymx, o));
    }
    if (lane == 0){
        s_red[warp][0]=sx;  s_red[warp][1]=sy;  s_red[warp][2]=sxy;
        s_red[warp][3]=sx2; s_red[warp][4]=sy2;
        s_red[warp][5]=xmn; s_red[warp][6]=xmx; s_red[warp][7]=ymn; s_red[warp][8]=ymx;
    }
    __syncthreads();
    if (tid == 0){
        double Sx=0,Sy=0,Sxy=0,Sx2=0,Sy2=0;
        float a = s_red[0][5], b = s_red[0][6], c = s_red[0][7], d = s_red[0][8];
        for (int w = 0; w < NWARP; w++){
            Sx+=s_red[w][0]; Sy+=s_red[w][1]; Sxy+=s_red[w][2];
            Sx2+=s_red[w][3]; Sy2+=s_red[w][4];
            a = fminf(a, s_red[w][5]); b = fmaxf(b, s_red[w][6]);
            c = fminf(c, s_red[w][7]); d = fmaxf(d, s_red[w][8]);
        }
        const double N = (double)NFULL;
        r_pear = 1.0 - (N*Sxy - Sx*Sy) / sqrt((N*Sx2 - Sx*Sx) * (N*Sy2 - Sy*Sy));
        s_mm[0]=a; s_mm[1]=b; s_mm[2]=c; s_mm[3]=d;
    }
    __syncthreads();

    // ---- pred FFT pass 1 (A -> C, L=1, twiddle-free) with MI histogram fused ----
    {
        const float xmin = s_mm[0], ymin = s_mm[2];
        const float bwx = __fdiv_rn(s_mm[1] - s_mm[0], 10.0f);
        const float bwy = __fdiv_rn(s_mm[3] - s_mm[2], 10.0f);
        int j = tid;
        float2 x[8];
        #pragma unroll
        for (int c = 0; c < 8; c++){
            int n = j + 1024*c;
            float2 a = make_float2(Ar[n], Ai[n]);
            float2 b = make_float2(Br[n], Bi[n]);
            x[c] = a;
            int ix0 = min(max((int)__fdiv_rn(a.x - xmin, bwx), 0), 9);
            int iy0 = min(max((int)__fdiv_rn(b.x - ymin, bwy), 0), 9);
            int ix1 = min(max((int)__fdiv_rn(a.y - xmin, bwx), 0), 9);
            int iy1 = min(max((int)__fdiv_rn(b.y - ymin, bwy), 0), 9);
            atomicAdd(&hist[ix0 * 10 + iy0], 1u);
            atomicAdd(&hist[ix1 * 10 + iy1], 1u);
        }
        fft8<0>(x);
        #pragma unroll
        for (int q = 0; q < 2; q++){
            ((float4*)(Cr + 8*j))[q] = make_float4(x[4*q].x, x[4*q+1].x, x[4*q+2].x, x[4*q+3].x);
            ((float4*)(Ci + 8*j))[q] = make_float4(x[4*q].y, x[4*q+1].y, x[4*q+2].y, x[4*q+3].y);
        }
    }
    __syncthreads();

    // ---- MI final math on warp 0 (hist stable; other warps proceed) ----
    if (warp == 0){
        const float eps = 1e-8f;
        const float invD = 1.0f / 8388608.0f;   // 1/(B*S), faithful to reference
        if (lane < 10){
            float hx = 0.f, hy = 0.f;
            for (int j = 0; j < 10; j++){
                hx += (float)hist[lane*10 + j];
                hy += (float)hist[j*10 + lane];
            }
            s_hx[lane] = hx; s_hy[lane] = hy;
        }
        __syncwarp();
        float mi = 0.f;
        for (int b = lane; b < 100; b += 32){
            float px  = s_hx[b/10] * invD;
            float py  = s_hy[b%10] * invD;
            float pxy = (float)hist[b] * invD;
            mi += pxy * logf(__fdiv_rn(pxy + eps, px * py + eps));
        }
        mi = warp_sum(mi);
        float he = 0.f;
        if (lane < 10){
            float px = s_hx[lane] * invD, py = s_hy[lane] * invD;
            he = -px * logf(px + eps) - py * logf(py + eps);
        }
        he = warp_sum(he);
        if (lane == 0) r_nmi = (double)(mi / (0.5f * he));
    }

    pass8<3,0,0,1>(Cr, Ci, Ar, Ai); __syncthreads();   // L=8,  swizzled writes
    pass8<6,0,1,0>(Ar, Ai, Cr, Ci); __syncthreads();   // L=64, swizzled reads
    pass8<9,0,0,0>(Cr, Ci, Ar, Ai); __syncthreads();   // L=512
    pass2<0>(Ar, Ai, Cr, Ci);       __syncthreads();   // pred spectrum in C

    // ---- targ forward FFT: B <-> A ----
    pass8<0,0,0,0>(Br, Bi, Ar, Ai); __syncthreads();
    pass8<3,0,0,1>(Ar, Ai, Br, Bi); __syncthreads();
    pass8<6,0,1,0>(Br, Bi, Ar, Ai); __syncthreads();
    pass8<9,0,0,0>(Ar, Ai, Br, Bi); __syncthreads();
    pass2<0>(Br, Bi, Ar, Ai);       __syncthreads();   // targ spectrum in A

    // ---- spectra: power-spectrum sums + hann-windowed phase correlation -> B ----
    float accd = 0.f, acct = 0.f;
    float2 lastX0p, lastX0t, lastXpp, lastXpt;
    for (int it = 0; it < 8; it++){
        int k = tid + it * 1024;               // 0..8191
        float2 w0 = eip<0>((float)k * (1.0f/8192.0f));
        float2 X0p = spec_at(Cr, Ci, k, w0);
        float2 X0t = spec_at(Ar, Ai, k, w0);
        float2 Xmp, Xmt, Xpp, Xpt;
        Xmp.x = __shfl_up_sync(0xffffffffu, X0p.x, 1);
        Xmp.y = __shfl_up_sync(0xffffffffu, X0p.y, 1);
        Xmt.x = __shfl_up_sync(0xffffffffu, X0t.x, 1);
        Xmt.y = __shfl_up_sync(0xffffffffu, X0t.y, 1);
        Xpp.x = __shfl_down_sync(0xffffffffu, X0p.x, 1);
        Xpp.y = __shfl_down_sync(0xffffffffu, X0p.y, 1);
        Xpt.x = __shfl_down_sync(0xffffffffu, X0t.x, 1);
        Xpt.y = __shfl_down_sync(0xffffffffu, X0t.y, 1);
        if (lane == 0){
            if (k == 0){
                float2 w1 = eip<0>(1.0f/8192.0f);
                Xmp = cconj(spec_at(Cr, Ci, 1, w1));   // X[-1] = conj(X[1])
                Xmt = cconj(spec_at(Ar, Ai, 1, w1));
            } else {
                float2 wm = eip<0>((float)(k-1) * (1.0f/8192.0f));
                Xmp = spec_at(Cr, Ci, k-1, wm);
                Xmt = spec_at(Ar, Ai, k-1, wm);
            }
        }
        if (lane == 31){
            float2 wp = eip<0>((float)(k+1) * (1.0f/8192.0f));
            Xpp = spec_at(Cr, Ci, k+1, wp);
            Xpt = spec_at(Ar, Ai, k+1, wp);
        }
        float pp = X0p.x*X0p.x + X0p.y*X0p.y;
        float pt = X0t.x*X0t.x + X0t.y*X0t.y;
        accd += fabsf(pp - pt);
        acct += pt;
        float2 xf = make_float2(0.5f*X0p.x - 0.25f*(Xmp.x + Xpp.x),
                                0.5f*X0p.y - 0.25f*(Xmp.y + Xpp.y));
        float2 tf = make_float2(0.5f*X0t.x - 0.25f*(Xmt.x + Xpt.x),
                                0.5f*X0t.y - 0.25f*(Xmt.y + Xpt.y));
        float2 c = cmul(xf, cconj(tf));
        float inv = rsqrtf(c.x*c.x + c.y*c.y);
        Br[k] = c.x * inv; Bi[k] = c.y * inv;
        lastX0p = X0p; lastX0t = X0t; lastXpp = Xpp; lastXpt = Xpt;
    }
    if (tid == THREADS - 1){
        // bin 8192: X0' = X[8192] (= lastXpp), Xm' = X[8191], Xp' = conj(X[8191])
        float2 X0p = lastXpp, X0t = lastXpt;
        float2 Xmp = lastX0p, Xmt = lastX0t;
        float2 Xpp = cconj(Xmp), Xpt = cconj(Xmt);
        float pp = X0p.x*X0p.x + X0p.y*X0p.y;
        float pt = X0t.x*X0t.x + X0t.y*X0t.y;
        accd += fabsf(pp - pt);
        acct += pt;
        float2 xf = make_float2(0.5f*X0p.x - 0.25f*(Xmp.x + Xpp.x),
                                0.5f*X0p.y - 0.25f*(Xmp.y + Xpp.y));
        float2 tf = make_float2(0.5f*X0t.x - 0.25f*(Xmt.x + Xpt.x),
                                0.5f*X0t.y - 0.25f*(Xmt.y + Xpt.y));
        float2 c = cmul(xf, cconj(tf));
        float inv = rsqrtf(c.x*c.x + c.y*c.y);
        s_c8192 = make_float2(c.x * inv, c.y * inv);
    }
    accd = warp_sum(accd); acct = warp_sum(acct);
    if (lane == 0){ s_red[warp][0] = accd; s_red[warp][1] = acct; }
    __syncthreads();
    if (tid == 0){
        double d = 0.0, t2 = 0.0;
        for (int w = 0; w < NWARP; w++){ d += s_red[w][0]; t2 += s_red[w][1]; }
        r_absd = d; r_tp = t2;
    }

    // ---- pack spectrum for real inverse FFT: B -> C (natural order) ----
    #pragma unroll 4
    for (int it = 0; it < 8; it++){
        int k = tid + it * 1024;
        float2 Ck = make_float2(Br[k], Bi[k]);
        float2 Ck2 = (k == 0) ? s_c8192
                              : make_float2(Br[8192 - k], -Bi[8192 - k]);  // conj(C[8192-k])
        float2 E = make_float2(0.5f*(Ck.x + Ck2.x), 0.5f*(Ck.y + Ck2.y));
        float2 D = make_float2(0.5f*(Ck.x - Ck2.x), 0.5f*(Ck.y - Ck2.y));
        float2 wn = eip<1>((float)k * (1.0f/8192.0f));   // e^{+i pi k/8192}
        float2 O  = cmul(wn, D);
        Cr[k] = E.x - O.y; Ci[k] = E.y + O.x;            // E + i*O
    }
    __syncthreads();

    // ---- inverse FFT chain: C <-> B ----
    pass8<0,1,0,0>(Cr, Ci, Br, Bi); __syncthreads();
    pass8<3,1,0,1>(Br, Bi, Cr, Ci); __syncthreads();
    pass8<6,1,1,0>(Cr, Ci, Br, Bi); __syncthreads();
    pass8<9,1,0,0>(Br, Bi, Cr, Ci); __syncthreads();
    pass2<1>(Cr, Ci, Br, Bi);       __syncthreads();   // time-domain in B

    // ---- argmax over 16384 real samples (first-occurrence tie break) ----
    float best = -INFINITY; int bi = 0x7fffffff;
    #pragma unroll 4
    for (int it = 0; it < 8; it++){
        int n = tid + it * 1024;
        float ze = Br[n], zo = Bi[n];     // y[2n], y[2n+1]
        int e = 2*n, o = 2*n + 1;
        if (ze > best || (ze == best && e < bi)){ best = ze; bi = e; }
        if (zo > best || (zo == best && o < bi)){ best = zo; bi = o; }
    }
    #pragma unroll
    for (int off = 16; off; off >>= 1){
        float ov = __shfl_down_sync(0xffffffffu, best, off);
        int   oi = __shfl_down_sync(0xffffffffu, bi,   off);
        if (ov > best || (ov == best && oi < bi)){ best = ov; bi = oi; }
    }
    if (lane == 0){ s_red[warp][0] = best; s_idx[warp] = bi; }
    __syncthreads();
    if (tid == 0){
        best = s_red[0][0]; bi = s_idx[0];
        for (int w = 1; w < NWARP; w++){
            float v = s_red[w][0]; int ix = s_idx[w];
            if (v > best || (v == best && ix < bi)){ best = v; bi = ix; }
        }
        r_cos = (double)cosf(2.0f * (float)PI_D * (float)bi / 16384.0f);

        // publish this row's results (release), then arrive
        g_row[row].pear = r_pear;
        g_row[row].cosv = r_cos;
        g_row[row].absd = r_absd;
        g_row[row].tp   = r_tp;
        g_row[row].nmi  = r_nmi;
        __threadfence();
        unsigned prev = atomicAdd(&g_done, 1u);
        s_last = ((prev % ROWS) == ROWS - 1) ? 1u : 0u;
        if (s_last) __threadfence();   // acquire: order g_row reads after counter observation
    }
    __syncthreads();

    // ---- last CTA reduces all rows and writes the scalar loss ----
    if (s_last){
        double pe = 0.0, co = 0.0, ad = 0.0, tp = 0.0, nm = 0.0;
        for (int r = tid; r < ROWS; r += THREADS){
            const double* p = (const double*)&g_row[r];
            pe += __ldcg(p + 0);
            co += __ldcg(p + 1);
            ad += __ldcg(p + 2);
            tp += __ldcg(p + 3);
            nm += __ldcg(p + 4);
        }
        pe = warp_sum_d(pe); co = warp_sum_d(co); ad = warp_sum_d(ad);
        tp = warp_sum_d(tp); nm = warp_sum_d(nm);
        if (lane == 0){
            s_fin[warp][0]=pe; s_fin[warp][1]=co; s_fin[warp][2]=ad;
            s_fin[warp][3]=tp; s_fin[warp][4]=nm;
        }
        __syncthreads();
        if (tid == 0){
            double Pe=0, Co=0, Ad=0, Tp=0, Nm=0;
            for (int w = 0; w < NWARP; w++){
                Pe+=s_fin[w][0]; Co+=s_fin[w][1]; Ad+=s_fin[w][2];
                Tp+=s_fin[w][3]; Nm+=s_fin[w][4];
            }
            int ep = *pep;
            double loss = Pe / (double)ROWS;
            if (ep >= 400){
                loss += 1.0 - Co / (double)ROWS;   // phase correlation
                loss += Ad / Tp;                   // power spectrum
            }
            if (ep >= 700){
                loss += 1.0 - Nm / (double)ROWS;   // mutual information
            }
            out[0] = (float)loss;
        }
    }
}

// ---------------- launch ----------------
extern "C" void kernel_launch(void* const* d_in, const int* in_sizes, int n_in,
                              void* d_out, int out_size){
    const float* pred = (const float*)d_in[0];
    const float* targ = (const float*)d_in[1];
    const int*   pi   = (const int*)d_in[2];
    const int*   pep  = (const int*)d_in[3];
    float* out = (float*)d_out;

    const size_t smem_bytes = (size_t)(6 * 8192) * sizeof(float);  // 196608
    cudaFuncSetAttribute(row_kernel, cudaFuncAttributeMaxDynamicSharedMemorySize,
                         (int)smem_bytes);

    row_kernel<<<ROWS, THREADS, smem_bytes>>>(pred, targ, pi, pep, out);
}

// round 11
// speedup vs baseline: 1.3625x; 1.3625x over previous
#include <cuda_runtime.h>
#include <math.h>
#include <stdint.h>

#define THREADS 512
#define NWARP 16
#define M 8192            // packed complex FFT size
#define NFULL 16384       // real signal length
#define ROWS 512
#define PI_D 3.14159265358979323846

// e^{-i pi/8192} (for W_16384 odd-index fixup)
#define K16C 0.99999992646571785f
#define K16S 0.00038349518757139556f

// ---------------- per-row outputs + completion counter (no allocation) --------
struct RowOut { double pear, cosv, absd, tp, nmi; };
__device__ RowOut  g_row[ROWS];
__device__ unsigned g_done = 0;    // monotonic across launches; (prev % ROWS) picks finalizer

// ---------------- complex helpers ----------------
__device__ __forceinline__ float2 cmul(float2 a, float2 b){
    return make_float2(a.x*b.x - a.y*b.y, a.x*b.y + a.y*b.x);
}
__device__ __forceinline__ float2 cadd(float2 a, float2 b){ return make_float2(a.x+b.x, a.y+b.y); }
__device__ __forceinline__ float2 csub(float2 a, float2 b){ return make_float2(a.x-b.x, a.y-b.y); }
__device__ __forceinline__ float2 cconj(float2 a){ return make_float2(a.x, -a.y); }

__device__ __forceinline__ float warp_sum(float v){
    #pragma unroll
    for (int o = 16; o; o >>= 1) v += __shfl_down_sync(0xffffffffu, v, o);
    return v;
}
__device__ __forceinline__ double warp_sum_d(double v){
    #pragma unroll
    for (int o = 16; o; o >>= 1) v += __shfl_down_sync(0xffffffffu, v, o);
    return v;
}

// ---------------- table twiddle fetch ----------------
// W_8192^k = e^{-2 pi i k / 8192}, k in [0, 8192); table holds k < 2048
template<int INV>
__device__ __forceinline__ float2 twget(const float2* __restrict__ Wt, int k){
    float2 w = Wt[k & 2047];
    int q = (k >> 11) & 3;
    float2 r = w;
    if (q == 1) r = make_float2( w.y, -w.x);
    else if (q == 2) r = make_float2(-w.x, -w.y);
    else if (q == 3) r = make_float2(-w.y,  w.x);
    if (INV) r.y = -r.y;
    return r;
}
// W_16384^k = e^{-i pi k / 8192}, k in [0, 8192]
template<int INV>
__device__ __forceinline__ float2 twget16k(const float2* __restrict__ Wt, int k){
    float2 w = twget<0>(Wt, k >> 1);
    if (k & 1) w = cmul(w, make_float2(K16C, -K16S));
    if (INV) w.y = -w.y;
    return w;
}

template<int INV>
__device__ __forceinline__ float2 cmulK(float2 a, float wr, float wi){
    float i2 = INV ? -wi : wi;
    return make_float2(a.x*wr - a.y*i2, a.x*i2 + a.y*wr);
}

// radix-4 DIT butterfly (natural-order DFT4)
template<int INV>
__device__ __forceinline__ void bfly4(float2 b0, float2 b1, float2 b2, float2 b3,
                                      float2& o0, float2& o1, float2& o2, float2& o3){
    float2 s  = cadd(b0, b2), d  = csub(b0, b2);
    float2 s2 = cadd(b1, b3), d2 = csub(b1, b3);
    o0 = cadd(s, s2); o2 = csub(s, s2);
    if (!INV){ o1 = make_float2(d.x + d2.y, d.y - d2.x); o3 = make_float2(d.x - d2.y, d.y + d2.x); }
    else     { o1 = make_float2(d.x - d2.y, d.y + d2.x); o3 = make_float2(d.x + d2.y, d.y - d2.x); }
}

// 16-point FFT in registers, natural in/out (two radix-4 micro-passes)
template<int INV>
__device__ __forceinline__ void fft16(float2* x){
    float2 t[16];
    #pragma unroll
    for (int g = 0; g < 4; g++)
        bfly4<INV>(x[g], x[g+4], x[g+8], x[g+12], t[4*g], t[4*g+1], t[4*g+2], t[4*g+3]);
    const float C1 = 0.9238795325112867f, S1 = 0.3826834323650898f, R2 = 0.7071067811865476f;
    bfly4<INV>(t[0], t[4], t[8], t[12], x[0], x[4], x[8], x[12]);
    bfly4<INV>(t[1], cmulK<INV>(t[5],  C1, -S1), cmulK<INV>(t[9],  R2, -R2), cmulK<INV>(t[13],  S1, -C1),
               x[1], x[5], x[9], x[13]);
    bfly4<INV>(t[2], cmulK<INV>(t[6],  R2, -R2), cmulK<INV>(t[10], 0.f, -1.f), cmulK<INV>(t[14], -R2, -R2),
               x[2], x[6], x[10], x[14]);
    bfly4<INV>(t[3], cmulK<INV>(t[7],  S1, -C1), cmulK<INV>(t[11], -R2, -R2), cmulK<INV>(t[15], -C1,  S1),
               x[3], x[7], x[11], x[15]);
}

// ---------------- buffer swizzles (bank-conflict elimination) ----------------
// SW=1: between pass16 writes (16j+c) and passR16<4> reads (j+512m) — conflict-free both sides.
// SW=2: between passR16<4> writes (r+16c+256s) and passR16<8> reads — conflict-free both sides.
template<int SW>
__device__ __forceinline__ int swz(int a){
    if (SW == 1) return a ^ ((a >> 4) & 31);
    if (SW == 2) return a ^ (((a >> 8) & 1) << 4);
    return a;
}

// Stockham radix-16 pass, L=1 (twiddle-free), natural reads, SW1 writes
template<int INV>
__device__ __forceinline__ void pass16p(const float* __restrict__ ri, const float* __restrict__ ii,
                                        float* __restrict__ ro, float* __restrict__ io){
    int j = threadIdx.x;
    float2 x[16];
    #pragma unroll
    for (int c = 0; c < 16; c++){ x[c].x = ri[j + 512*c]; x[c].y = ii[j + 512*c]; }
    fft16<INV>(x);
    #pragma unroll
    for (int c = 0; c < 16; c++){
        int a = swz<1>(16*j + c);
        ro[a] = x[c].x; io[a] = x[c].y;
    }
}

// Stockham radix-16 pass at sub-length L = 2^LOG2L (L in {16, 256}), w1 from tiny table
template<int LOG2L, int INV, int SWR, int SWW>
__device__ __forceinline__ void passR16(const float* __restrict__ ri, const float* __restrict__ ii,
                                        float* __restrict__ ro, float* __restrict__ io,
                                        const float2* __restrict__ wtab){
    const int L = 1 << LOG2L;
    int j = threadIdx.x;
    int r = j & (L - 1);
    int s = j >> LOG2L;
    float2 x[16];
    #pragma unroll
    for (int m = 0; m < 16; m++){
        int a = swz<SWR>(j + 512*m);
        x[m].x = ri[a]; x[m].y = ii[a];
    }
    float2 w1 = wtab[r];
    if (INV) w1.y = -w1.y;
    float2 w2 = cmul(w1, w1);
    float2 w3 = cmul(w2, w1);
    float2 w4 = cmul(w2, w2);
    float2 w8 = cmul(w4, w4);
    x[1]  = cmul(x[1],  w1);
    x[2]  = cmul(x[2],  w2);
    x[3]  = cmul(x[3],  w3);
    x[4]  = cmul(x[4],  w4);
    x[5]  = cmul(x[5],  cmul(w4, w1));
    x[6]  = cmul(x[6],  cmul(w4, w2));
    x[7]  = cmul(x[7],  cmul(w4, w3));
    x[8]  = cmul(x[8],  w8);
    x[9]  = cmul(x[9],  cmul(w8, w1));
    x[10] = cmul(x[10], cmul(w8, w2));
    x[11] = cmul(x[11], cmul(w8, w3));
    x[12] = cmul(x[12], cmul(w8, w4));
    x[13] = cmul(x[13], cmul(w8, cmul(w4, w1)));
    x[14] = cmul(x[14], cmul(w8, cmul(w4, w2)));
    x[15] = cmul(x[15], cmul(w8, cmul(w4, w3)));
    fft16<INV>(x);
    int base = r + (s << (LOG2L + 4));
    #pragma unroll
    for (int c = 0; c < 16; c++){
        int a = swz<SWW>(base + (c << LOG2L));
        ro[a] = x[c].x; io[a] = x[c].y;
    }
}

// final Stockham radix-2 pass (L=4096), forward chains only (inverse one is folded into argmax)
template<int INV>
__device__ __forceinline__ void pass2(const float* __restrict__ ri, const float* __restrict__ ii,
                                      float* __restrict__ ro, float* __restrict__ io,
                                      const float2* __restrict__ Wt){
    #pragma unroll
    for (int it = 0; it < 8; it++){
        int j = threadIdx.x + it * 512;
        float2 a = make_float2(ri[j], ii[j]);
        float2 b = make_float2(ri[j + 4096], ii[j + 4096]);
        float2 v = cmul(b, twget<INV>(Wt, j));
        ro[j] = a.x + v.x;        io[j] = a.y + v.y;
        ro[j + 4096] = a.x - v.x; io[j + 4096] = a.y - v.y;
    }
}

// unpack X[k] of the length-16384 real signal from packed spectrum planes
__device__ __forceinline__ float2 spec_at(const float* __restrict__ re, const float* __restrict__ im,
                                          int k, float2 w){
    int k1 = k & (M - 1), k2 = (M - k) & (M - 1);
    float2 a = make_float2(re[k1], im[k1]);
    float2 b = make_float2(re[k2], im[k2]);
    float2 E = make_float2(0.5f*(a.x + b.x),  0.5f*(a.y - b.y));
    float2 O = make_float2(0.5f*(a.y + b.y), -0.5f*(a.x - b.x));
    float2 WO = cmul(w, O);
    return make_float2(E.x + WO.x, E.y + WO.y);
}

// ---------------- single fused kernel: one CTA per row, last CTA finalizes ----
__global__ __launch_bounds__(THREADS, 1)
void row_kernel(const float* __restrict__ pred, const float* __restrict__ targ,
                const int* __restrict__ pi, const int* __restrict__ pep,
                float* __restrict__ out){
    extern __shared__ float smf[];
    float* Ar = smf;
    float* Ai = smf + 8192;
    float* Br = smf + 16384;
    float* Bi = smf + 24576;
    float* Cr = smf + 32768;
    float* Ci = smf + 40960;
    float2* Wt  = (float2*)(smf + 49152);   // 2048 entries: W_8192^k, k<2048
    float2* w4t = (float2*)(smf + 53248);   // 16 entries:   e^{-i pi r/128}
    float2* w8t = (float2*)(smf + 53280);   // 256 entries:  e^{-i pi r/2048}

    __shared__ float    s_red[NWARP][10];
    __shared__ int      s_idx[NWARP];
    __shared__ float    s_mm[4];
    __shared__ unsigned hist[100];
    __shared__ float    s_hx[10], s_hy[10];
    __shared__ float2   s_c8192;
    __shared__ unsigned s_last;
    __shared__ double   s_fin[NWARP][5];

    const int tid  = threadIdx.x;
    const int warp = tid >> 5, lane = tid & 31;
    const int row  = blockIdx.x;
    const int i0   = *pi;

    double r_pear = 0.0, r_cos = 0.0, r_absd = 0.0, r_tp = 0.0, r_nmi = 0.0;

    const float2* xr = (const float2*)(pred + ((size_t)i0 * ROWS + row) * (size_t)NFULL);
    const float2* yr = (const float2*)(targ + (size_t)row * (size_t)NFULL);

    if (tid < 100) hist[tid] = 0u;

    // ---- one-time twiddle tables (accurate sincospif; ~5 calls/thread) ----
    #pragma unroll
    for (int it = 0; it < 4; it++){
        int t = tid + it * 512;
        float s, c; sincospif(-(float)t * (1.0f/4096.0f), &s, &c);
        Wt[t] = make_float2(c, s);
    }
    if (tid < 16){ float s, c; sincospif(-(float)tid * (1.0f/128.0f),  &s, &c); w4t[tid] = make_float2(c, s); }
    if (tid < 256){ float s, c; sincospif(-(float)tid * (1.0f/2048.0f), &s, &c); w8t[tid] = make_float2(c, s); }

    // ---- load (SoA natural order) + Pearson moments + min/max ----
    float sx = 0.f, sy = 0.f, sxy = 0.f, sx2 = 0.f, sy2 = 0.f;
    float xmn = INFINITY, xmx = -INFINITY, ymn = INFINITY, ymx = -INFINITY;
    #pragma unroll 4
    for (int it = 0; it < 16; it++){
        int n = tid + it * THREADS;
        float2 a = xr[n], b = yr[n];
        sx  += a.x + a.y;          sy  += b.x + b.y;
        sxy += a.x*b.x + a.y*b.y;
        sx2 += a.x*a.x + a.y*a.y;  sy2 += b.x*b.x + b.y*b.y;
        xmn = fminf(xmn, fminf(a.x, a.y)); xmx = fmaxf(xmx, fmaxf(a.x, a.y));
        ymn = fminf(ymn, fminf(b.x, b.y)); ymx = fmaxf(ymx, fmaxf(b.x, b.y));
        Ar[n] = a.x; Ai[n] = a.y;
        Br[n] = b.x; Bi[n] = b.y;
    }
    sx  = warp_sum(sx);  sy  = warp_sum(sy); sxy = warp_sum(sxy);
    sx2 = warp_sum(sx2); sy2 = warp_sum(sy2);
    #pragma unroll
    for (int o = 16; o; o >>= 1){
        xmn = fminf(xmn, __shfl_down_sync(0xffffffffu, xmn, o));
        xmx = fmaxf(xmx, __shfl_down_sync(0xffffffffu, xmx, o));
        ymn = fminf(ymn, __shfl_down_sync(0xffffffffu, ymn, o));
        ymx = fmaxf(ymx, __shfl_down_sync(0xffffffffu, ymx, o));
    }
    if (lane == 0){
        s_red[warp][0]=sx;  s_red[warp][1]=sy;  s_red[warp][2]=sxy;
        s_red[warp][3]=sx2; s_red[warp][4]=sy2;
        s_red[warp][5]=xmn; s_red[warp][6]=xmx; s_red[warp][7]=ymn; s_red[warp][8]=ymx;
    }
    __syncthreads();
    if (tid == 0){
        double Sx=0,Sy=0,Sxy=0,Sx2=0,Sy2=0;
        float a = s_red[0][5], b = s_red[0][6], c = s_red[0][7], d = s_red[0][8];
        for (int w = 0; w < NWARP; w++){
            Sx+=s_red[w][0]; Sy+=s_red[w][1]; Sxy+=s_red[w][2];
            Sx2+=s_red[w][3]; Sy2+=s_red[w][4];
            a = fminf(a, s_red[w][5]); b = fmaxf(b, s_red[w][6]);
            c = fminf(c, s_red[w][7]); d = fmaxf(d, s_red[w][8]);
        }
        const double N = (double)NFULL;
        r_pear = 1.0 - (N*Sxy - Sx*Sy) / sqrt((N*Sx2 - Sx*Sx) * (N*Sy2 - Sy*Sy));
        s_mm[0]=a; s_mm[1]=b; s_mm[2]=c; s_mm[3]=d;
    }
    __syncthreads();

    // ---- pred FFT pass 1 (A -> C, L=1) with MI histogram fused ----
    {
        const float xmin = s_mm[0], ymin = s_mm[2];
        const float bwx = __fdiv_rn(s_mm[1] - s_mm[0], 10.0f);
        const float bwy = __fdiv_rn(s_mm[3] - s_mm[2], 10.0f);
        int j = tid;
        float2 x[16];
        #pragma unroll
        for (int c = 0; c < 16; c++){
            int n = j + 512*c;
            float2 a = make_float2(Ar[n], Ai[n]);
            float2 b = make_float2(Br[n], Bi[n]);
            x[c] = a;
            int ix0 = min(max((int)__fdiv_rn(a.x - xmin, bwx), 0), 9);
            int iy0 = min(max((int)__fdiv_rn(b.x - ymin, bwy), 0), 9);
            int ix1 = min(max((int)__fdiv_rn(a.y - xmin, bwx), 0), 9);
            int iy1 = min(max((int)__fdiv_rn(b.y - ymin, bwy), 0), 9);
            atomicAdd(&hist[ix0 * 10 + iy0], 1u);
            atomicAdd(&hist[ix1 * 10 + iy1], 1u);
        }
        fft16<0>(x);
        #pragma unroll
        for (int c = 0; c < 16; c++){
            int a = swz<1>(16*j + c);
            Cr[a] = x[c].x; Ci[a] = x[c].y;
        }
    }
    __syncthreads();

    // ---- MI final math on warp 0 (hist stable; other warps proceed) ----
    if (warp == 0){
        const float eps = 1e-8f;
        const float invD = 1.0f / 8388608.0f;   // 1/(B*S), faithful to reference
        if (lane < 10){
            float hx = 0.f, hy = 0.f;
            for (int j = 0; j < 10; j++){
                hx += (float)hist[lane*10 + j];
                hy += (float)hist[j*10 + lane];
            }
            s_hx[lane] = hx; s_hy[lane] = hy;
        }
        __syncwarp();
        float mi = 0.f;
        for (int b = lane; b < 100; b += 32){
            float px  = s_hx[b/10] * invD;
            float py  = s_hy[b%10] * invD;
            float pxy = (float)hist[b] * invD;
            mi += pxy * logf(__fdiv_rn(pxy + eps, px * py + eps));
        }
        mi = warp_sum(mi);
        float he = 0.f;
        if (lane < 10){
            float px = s_hx[lane] * invD, py = s_hy[lane] * invD;
            he = -px * logf(px + eps) - py * logf(py + eps);
        }
        he = warp_sum(he);
        if (lane == 0) r_nmi = (double)(mi / (0.5f * he));
    }

    passR16<4,0,1,2>(Cr, Ci, Ar, Ai, w4t); __syncthreads();
    passR16<8,0,2,0>(Ar, Ai, Cr, Ci, w8t); __syncthreads();
    pass2<0>(Cr, Ci, Ar, Ai, Wt);          __syncthreads();   // pred spectrum in A

    // ---- targ forward FFT: B <-> C ----
    pass16p<0>(Br, Bi, Cr, Ci);            __syncthreads();
    passR16<4,0,1,2>(Cr, Ci, Br, Bi, w4t); __syncthreads();
    passR16<8,0,2,0>(Br, Bi, Cr, Ci, w8t); __syncthreads();
    pass2<0>(Cr, Ci, Br, Bi, Wt);          __syncthreads();   // targ spectrum in B

    // ---- spectra: power-spectrum sums + hann-windowed phase correlation -> C ----
    float accd = 0.f, acct = 0.f;
    float2 lastX0p, lastX0t, lastXpp, lastXpt;
    for (int it = 0; it < 16; it++){
        int k = tid + it * 512;               // 0..8191
        float2 w0 = twget16k<0>(Wt, k);
        float2 X0p = spec_at(Ar, Ai, k, w0);
        float2 X0t = spec_at(Br, Bi, k, w0);
        float2 Xmp, Xmt, Xpp, Xpt;
        Xmp.x = __shfl_up_sync(0xffffffffu, X0p.x, 1);
        Xmp.y = __shfl_up_sync(0xffffffffu, X0p.y, 1);
        Xmt.x = __shfl_up_sync(0xffffffffu, X0t.x, 1);
        Xmt.y = __shfl_up_sync(0xffffffffu, X0t.y, 1);
        Xpp.x = __shfl_down_sync(0xffffffffu, X0p.x, 1);
        Xpp.y = __shfl_down_sync(0xffffffffu, X0p.y, 1);
        Xpt.x = __shfl_down_sync(0xffffffffu, X0t.x, 1);
        Xpt.y = __shfl_down_sync(0xffffffffu, X0t.y, 1);
        if (lane == 0){
            if (k == 0){
                float2 w1 = twget16k<0>(Wt, 1);
                Xmp = cconj(spec_at(Ar, Ai, 1, w1));   // X[-1] = conj(X[1])
                Xmt = cconj(spec_at(Br, Bi, 1, w1));
            } else {
                float2 wm = twget16k<0>(Wt, k-1);
                Xmp = spec_at(Ar, Ai, k-1, wm);
                Xmt = spec_at(Br, Bi, k-1, wm);
            }
        }
        if (lane == 31){
            float2 wp = twget16k<0>(Wt, k+1);
            Xpp = spec_at(Ar, Ai, k+1, wp);
            Xpt = spec_at(Br, Bi, k+1, wp);
        }
        float pp = X0p.x*X0p.x + X0p.y*X0p.y;
        float pt = X0t.x*X0t.x + X0t.y*X0t.y;
        accd += fabsf(pp - pt);
        acct += pt;
        float2 xf = make_float2(0.5f*X0p.x - 0.25f*(Xmp.x + Xpp.x),
                                0.5f*X0p.y - 0.25f*(Xmp.y + Xpp.y));
        float2 tf = make_float2(0.5f*X0t.x - 0.25f*(Xmt.x + Xpt.x),
                                0.5f*X0t.y - 0.25f*(Xmt.y + Xpt.y));
        float2 c = cmul(xf, cconj(tf));
        float inv = rsqrtf(c.x*c.x + c.y*c.y);
        Cr[k] = c.x * inv; Ci[k] = c.y * inv;
        lastX0p = X0p; lastX0t = X0t; lastXpp = Xpp; lastXpt = Xpt;
    }
    if (tid == THREADS - 1){
        // bin 8192: X0' = X[8192] (= lastXpp), Xm' = X[8191], Xp' = conj(X[8191])
        float2 X0p = lastXpp, X0t = lastXpt;
        float2 Xmp = lastX0p, Xmt = lastX0t;
        float2 Xpp = cconj(Xmp), Xpt = cconj(Xmt);
        float pp = X0p.x*X0p.x + X0p.y*X0p.y;
        float pt = X0t.x*X0t.x + X0t.y*X0t.y;
        accd += fabsf(pp - pt);
        acct += pt;
        float2 xf = make_float2(0.5f*X0p.x - 0.25f*(Xmp.x + Xpp.x),
                                0.5f*X0p.y - 0.25f*(Xmp.y + Xpp.y));
        float2 tf = make_float2(0.5f*X0t.x - 0.25f*(Xmt.x + Xpt.x),
                                0.5f*X0t.y - 0.25f*(Xmt.y + Xpt.y));
        float2 c = cmul(xf, cconj(tf));
        float inv = rsqrtf(c.x*c.x + c.y*c.y);
        s_c8192 = make_float2(c.x * inv, c.y * inv);
    }
    accd = warp_sum(accd); acct = warp_sum(acct);
    if (lane == 0){ s_red[warp][0] = accd; s_red[warp][1] = acct; }
    __syncthreads();
    if (tid == 0){
        double d = 0.0, t2 = 0.0;
        for (int w = 0; w < NWARP; w++){ d += s_red[w][0]; t2 += s_red[w][1]; }
        r_absd = d; r_tp = t2;
    }

    // ---- inverse pass 1 with spectrum-pack folded in: C -> A (SW1 writes) ----
    {
        int j = tid;
        float2 x[16];
        #pragma unroll
        for (int c = 0; c < 16; c++){
            int n = j + 512*c;
            float2 Bn = make_float2(Cr[n], Ci[n]);
            float2 Bm = (n == 0) ? s_c8192
                                 : make_float2(Cr[8192 - n], -Ci[8192 - n]);  // conj(C[8192-n])
            float2 E = make_float2(0.5f*(Bn.x + Bm.x), 0.5f*(Bn.y + Bm.y));
            float2 D = make_float2(0.5f*(Bn.x - Bm.x), 0.5f*(Bn.y - Bm.y));
            float2 wn = twget16k<1>(Wt, n);          // e^{+i pi n/8192}
            float2 O  = cmul(wn, D);
            x[c] = make_float2(E.x - O.y, E.y + O.x);  // E + i*O
        }
        fft16<1>(x);
        #pragma unroll
        for (int c = 0; c < 16; c++){
            int a = swz<1>(16*j + c);
            Ar[a] = x[c].x; Ai[a] = x[c].y;
        }
    }
    __syncthreads();

    passR16<4,1,1,2>(Ar, Ai, Cr, Ci, w4t); __syncthreads();
    passR16<8,1,2,0>(Cr, Ci, Ar, Ai, w8t); __syncthreads();  // inverse penultimate in A

    // ---- argmax with final radix-2 pass folded in (first-occurrence tie break) ----
    float best = -INFINITY; int bi = 0x7fffffff;
    #pragma unroll 2
    for (int it = 0; it < 8; it++){
        int jj = tid + it * 512;              // 0..4095
        float2 u = make_float2(Ar[jj], Ai[jj]);
        float2 v = make_float2(Ar[jj + 4096], Ai[jj + 4096]);
        float2 wv = cmul(v, twget<1>(Wt, jj));
        float y0r = u.x + wv.x, y0i = u.y + wv.y;   // Z[jj]      -> times 2jj, 2jj+1
        float y1r = u.x - wv.x, y1i = u.y - wv.y;   // Z[jj+4096] -> times 2jj+8192, +8193
        int e0 = 2*jj, o0 = 2*jj + 1, e1 = 2*jj + 8192, o1 = 2*jj + 8193;
        if (y0r > best || (y0r == best && e0 < bi)){ best = y0r; bi = e0; }
        if (y0i > best || (y0i == best && o0 < bi)){ best = y0i; bi = o0; }
        if (y1r > best || (y1r == best && e1 < bi)){ best = y1r; bi = e1; }
        if (y1i > best || (y1i == best && o1 < bi)){ best = y1i; bi = o1; }
    }
    #pragma unroll
    for (int off = 16; off; off >>= 1){
        float ov = __shfl_down_sync(0xffffffffu, best, off);
        int   oi = __shfl_down_sync(0xffffffffu, bi,   off);
        if (ov > best || (ov == best && oi < bi)){ best = ov; bi = oi; }
    }
    if (lane == 0){ s_red[warp][0] = best; s_idx[warp] = bi; }
    __syncthreads();
    if (tid == 0){
        best = s_red[0][0]; bi = s_idx[0];
        for (int w = 1; w < NWARP; w++){
            float v = s_red[w][0]; int ix = s_idx[w];
            if (v > best || (v == best && ix < bi)){ best = v; bi = ix; }
        }
        r_cos = (double)cosf(2.0f * (float)PI_D * (float)bi / 16384.0f);

        // publish this row's results (release), then arrive
        g_row[row].pear = r_pear;
        g_row[row].cosv = r_cos;
        g_row[row].absd = r_absd;
        g_row[row].tp   = r_tp;
        g_row[row].nmi  = r_nmi;
        __threadfence();
        unsigned prev = atomicAdd(&g_done, 1u);
        s_last = ((prev % ROWS) == ROWS - 1) ? 1u : 0u;
        if (s_last) __threadfence();   // acquire: order g_row reads after counter observation
    }
    __syncthreads();

    // ---- last CTA reduces all rows and writes the scalar loss ----
    if (s_last){
        double pe = 0.0, co = 0.0, ad = 0.0, tp = 0.0, nm = 0.0;
        for (int r = tid; r < ROWS; r += THREADS){
            const double* p = (const double*)&g_row[r];
            pe += __ldcg(p + 0);
            co += __ldcg(p + 1);
            ad += __ldcg(p + 2);
            tp += __ldcg(p + 3);
            nm += __ldcg(p + 4);
        }
        pe = warp_sum_d(pe); co = warp_sum_d(co); ad = warp_sum_d(ad);
        tp = warp_sum_d(tp); nm = warp_sum_d(nm);
        if (lane == 0){
            s_fin[warp][0]=pe; s_fin[warp][1]=co; s_fin[warp][2]=ad;
            s_fin[warp][3]=tp; s_fin[warp][4]=nm;
        }
        __syncthreads();
        if (tid == 0){
            double Pe=0, Co=0, Ad=0, Tp=0, Nm=0;
            for (int w = 0; w < NWARP; w++){
                Pe+=s_fin[w][0]; Co+=s_fin[w][1]; Ad+=s_fin[w][2];
                Tp+=s_fin[w][3]; Nm+=s_fin[w][4];
            }
            int ep = *pep;
            double loss = Pe / (double)ROWS;
            if (ep >= 400){
                loss += 1.0 - Co / (double)ROWS;   // phase correlation
                loss += Ad / Tp;                   // power spectrum
            }
            if (ep >= 700){
                loss += 1.0 - Nm / (double)ROWS;   // mutual information
            }
            out[0] = (float)loss;
        }
    }
}

// ---------------- launch ----------------
extern "C" void kernel_launch(void* const* d_in, const int* in_sizes, int n_in,
                              void* d_out, int out_size){
    const float* pred = (const float*)d_in[0];
    const float* targ = (const float*)d_in[1];
    const int*   pi   = (const int*)d_in[2];
    const int*   pep  = (const int*)d_in[3];
    float* out = (float*)d_out;

    // 6 planes of 8192 floats + 2048+16+256 float2 twiddles
    const size_t smem_bytes = (size_t)(49152 + 2*(2048 + 16 + 256)) * sizeof(float); // 215168
    cudaFuncSetAttribute(row_kernel, cudaFuncAttributeMaxDynamicSharedMemorySize,
                         (int)smem_bytes);

    row_kernel<<<ROWS, THREADS, smem_bytes>>>(pred, targ, pi, pep, out);
}

// round 12
// speedup vs baseline: 1.4171x; 1.0401x over previous
#include <cuda_runtime.h>
#include <math.h>
#include <stdint.h>

#define THREADS 512
#define NWARP 16
#define M 8192            // packed complex FFT size
#define NFULL 16384       // real signal length
#define ROWS 512
#define PI_D 3.14159265358979323846

// e^{-i pi/8192} (for W_16384 odd-index fixup)
#define K16C 0.99999992646571785f
#define K16S 0.00038349518757139556f

// ---------------- per-row outputs + completion counter (no allocation) --------
struct RowOut { double pear, cosv, absd, tp, nmi; };
__device__ RowOut  g_row[ROWS];
__device__ unsigned g_done = 0;    // monotonic across launches; (prev % ROWS) picks finalizer

// ---------------- complex helpers ----------------
__device__ __forceinline__ float2 cmul(float2 a, float2 b){
    return make_float2(a.x*b.x - a.y*b.y, a.x*b.y + a.y*b.x);
}
__device__ __forceinline__ float2 cadd(float2 a, float2 b){ return make_float2(a.x+b.x, a.y+b.y); }
__device__ __forceinline__ float2 csub(float2 a, float2 b){ return make_float2(a.x-b.x, a.y-b.y); }
__device__ __forceinline__ float2 cconj(float2 a){ return make_float2(a.x, -a.y); }

__device__ __forceinline__ float warp_sum(float v){
    #pragma unroll
    for (int o = 16; o; o >>= 1) v += __shfl_down_sync(0xffffffffu, v, o);
    return v;
}
__device__ __forceinline__ double warp_sum_d(double v){
    #pragma unroll
    for (int o = 16; o; o >>= 1) v += __shfl_down_sync(0xffffffffu, v, o);
    return v;
}

// ---------------- table twiddle fetch ----------------
// W_8192^k = e^{-2 pi i k / 8192}, k in [0, 8192); table holds k < 2048
template<int INV>
__device__ __forceinline__ float2 twget(const float2* __restrict__ Wt, int k){
    float2 w = Wt[k & 2047];
    int q = (k >> 11) & 3;
    float2 r = w;
    if (q == 1) r = make_float2( w.y, -w.x);
    else if (q == 2) r = make_float2(-w.x, -w.y);
    else if (q == 3) r = make_float2(-w.y,  w.x);
    if (INV) r.y = -r.y;
    return r;
}
// W_16384^k = e^{-i pi k / 8192}, k in [0, 8192]
template<int INV>
__device__ __forceinline__ float2 twget16k(const float2* __restrict__ Wt, int k){
    float2 w = twget<0>(Wt, k >> 1);
    if (k & 1) w = cmul(w, make_float2(K16C, -K16S));
    if (INV) w.y = -w.y;
    return w;
}

template<int INV>
__device__ __forceinline__ float2 cmulK(float2 a, float wr, float wi){
    float i2 = INV ? -wi : wi;
    return make_float2(a.x*wr - a.y*i2, a.x*i2 + a.y*wr);
}

// radix-4 DIT butterfly (natural-order DFT4)
template<int INV>
__device__ __forceinline__ void bfly4(float2 b0, float2 b1, float2 b2, float2 b3,
                                      float2& o0, float2& o1, float2& o2, float2& o3){
    float2 s  = cadd(b0, b2), d  = csub(b0, b2);
    float2 s2 = cadd(b1, b3), d2 = csub(b1, b3);
    o0 = cadd(s, s2); o2 = csub(s, s2);
    if (!INV){ o1 = make_float2(d.x + d2.y, d.y - d2.x); o3 = make_float2(d.x - d2.y, d.y + d2.x); }
    else     { o1 = make_float2(d.x - d2.y, d.y + d2.x); o3 = make_float2(d.x + d2.y, d.y - d2.x); }
}

// 16-point FFT in registers, natural in/out (two radix-4 micro-passes)
template<int INV>
__device__ __forceinline__ void fft16(float2* x){
    float2 t[16];
    #pragma unroll
    for (int g = 0; g < 4; g++)
        bfly4<INV>(x[g], x[g+4], x[g+8], x[g+12], t[4*g], t[4*g+1], t[4*g+2], t[4*g+3]);
    const float C1 = 0.9238795325112867f, S1 = 0.3826834323650898f, R2 = 0.7071067811865476f;
    bfly4<INV>(t[0], t[4], t[8], t[12], x[0], x[4], x[8], x[12]);
    bfly4<INV>(t[1], cmulK<INV>(t[5],  C1, -S1), cmulK<INV>(t[9],  R2, -R2), cmulK<INV>(t[13],  S1, -C1),
               x[1], x[5], x[9], x[13]);
    bfly4<INV>(t[2], cmulK<INV>(t[6],  R2, -R2), cmulK<INV>(t[10], 0.f, -1.f), cmulK<INV>(t[14], -R2, -R2),
               x[2], x[6], x[10], x[14]);
    bfly4<INV>(t[3], cmulK<INV>(t[7],  S1, -C1), cmulK<INV>(t[11], -R2, -R2), cmulK<INV>(t[15], -C1,  S1),
               x[3], x[7], x[11], x[15]);
}

// ---------------- element swizzle (AoS float2 planes) ----------------
// Needed ONLY for the digit-reversal write pattern 16j+c (16-way phase conflict
// in AoS); all strided patterns (j+512m, r+(c<<L), j/j+4096) are naturally
// conflict-free under 64-bit half-warp phasing.
__device__ __forceinline__ int swz1(int a){ return a ^ ((a >> 4) & 31); }

// Stockham radix-16 pass, L=1 (twiddle-free), natural reads, swz1 writes
template<int INV>
__device__ __forceinline__ void pass16p(const float2* __restrict__ zi, float2* __restrict__ zo){
    int j = threadIdx.x;
    float2 x[16];
    #pragma unroll
    for (int c = 0; c < 16; c++) x[c] = zi[j + 512*c];
    fft16<INV>(x);
    #pragma unroll
    for (int c = 0; c < 16; c++) zo[swz1(16*j + c)] = x[c];
}

// Stockham radix-16 pass at sub-length L = 2^LOG2L (L in {16, 256}), w1 from tiny table.
// SWR=1 when the producer wrote with swz1 (i.e. the L=16 pass).
template<int LOG2L, int INV, int SWR>
__device__ __forceinline__ void passR16(const float2* __restrict__ zi, float2* __restrict__ zo,
                                        const float2* __restrict__ wtab){
    const int L = 1 << LOG2L;
    int j = threadIdx.x;
    int r = j & (L - 1);
    int s = j >> LOG2L;
    float2 x[16];
    #pragma unroll
    for (int m = 0; m < 16; m++){
        int a = j + 512*m;
        if (SWR) a = swz1(a);
        x[m] = zi[a];
    }
    float2 w1 = wtab[r];
    if (INV) w1.y = -w1.y;
    float2 w2 = cmul(w1, w1);
    float2 w3 = cmul(w2, w1);
    float2 w4 = cmul(w2, w2);
    float2 w8 = cmul(w4, w4);
    x[1]  = cmul(x[1],  w1);
    x[2]  = cmul(x[2],  w2);
    x[3]  = cmul(x[3],  w3);
    x[4]  = cmul(x[4],  w4);
    x[5]  = cmul(x[5],  cmul(w4, w1));
    x[6]  = cmul(x[6],  cmul(w4, w2));
    x[7]  = cmul(x[7],  cmul(w4, w3));
    x[8]  = cmul(x[8],  w8);
    x[9]  = cmul(x[9],  cmul(w8, w1));
    x[10] = cmul(x[10], cmul(w8, w2));
    x[11] = cmul(x[11], cmul(w8, w3));
    x[12] = cmul(x[12], cmul(w8, w4));
    x[13] = cmul(x[13], cmul(w8, cmul(w4, w1)));
    x[14] = cmul(x[14], cmul(w8, cmul(w4, w2)));
    x[15] = cmul(x[15], cmul(w8, cmul(w4, w3)));
    fft16<INV>(x);
    int base = r + (s << (LOG2L + 4));
    #pragma unroll
    for (int c = 0; c < 16; c++)
        zo[base + (c << LOG2L)] = x[c];
}

// final Stockham radix-2 pass (L=4096), forward chains only
template<int INV>
__device__ __forceinline__ void pass2(const float2* __restrict__ zi, float2* __restrict__ zo,
                                      const float2* __restrict__ Wt){
    #pragma unroll
    for (int it = 0; it < 8; it++){
        int j = threadIdx.x + it * 512;
        float2 a = zi[j];
        float2 v = cmul(zi[j + 4096], twget<INV>(Wt, j));
        zo[j]        = cadd(a, v);
        zo[j + 4096] = csub(a, v);
    }
}

// unpack X[k] of the length-16384 real signal from the packed spectrum plane
__device__ __forceinline__ float2 spec_at(const float2* __restrict__ Z, int k, float2 w){
    float2 a = Z[k & (M - 1)];
    float2 b = Z[(M - k) & (M - 1)];
    float2 E = make_float2(0.5f*(a.x + b.x),  0.5f*(a.y - b.y));
    float2 O = make_float2(0.5f*(a.y + b.y), -0.5f*(a.x - b.x));
    float2 WO = cmul(w, O);
    return make_float2(E.x + WO.x, E.y + WO.y);
}

// ---------------- single fused kernel: one CTA per row, last CTA finalizes ----
__global__ __launch_bounds__(THREADS, 1)
void row_kernel(const float* __restrict__ pred, const float* __restrict__ targ,
                const int* __restrict__ pi, const int* __restrict__ pep,
                float* __restrict__ out){
    extern __shared__ float2 smz[];
    float2* Ap = smz;               // 8192
    float2* Bp = smz + 8192;        // 8192
    float2* Cp = smz + 16384;       // 8192
    float2* Wt  = smz + 24576;      // 2048: W_8192^k, k<2048
    float2* w4t = smz + 26624;      // 16:   e^{-i pi r/128}
    float2* w8t = smz + 26640;      // 256:  e^{-i pi r/2048}

    __shared__ float    s_red[NWARP][10];
    __shared__ int      s_idx[NWARP];
    __shared__ float    s_mm[4];
    __shared__ unsigned hist[100];
    __shared__ float    s_hx[10], s_hy[10];
    __shared__ float2   s_c8192;
    __shared__ unsigned s_last;
    __shared__ double   s_fin[NWARP][5];

    const int tid  = threadIdx.x;
    const int warp = tid >> 5, lane = tid & 31;
    const int row  = blockIdx.x;
    const int i0   = *pi;

    double r_pear = 0.0, r_cos = 0.0, r_absd = 0.0, r_tp = 0.0, r_nmi = 0.0;

    const float2* xr = (const float2*)(pred + ((size_t)i0 * ROWS + row) * (size_t)NFULL);
    const float2* yr = (const float2*)(targ + (size_t)row * (size_t)NFULL);

    if (tid < 100) hist[tid] = 0u;

    // ---- one-time twiddle tables (accurate sincospif; ~5 calls/thread) ----
    #pragma unroll
    for (int it = 0; it < 4; it++){
        int t = tid + it * 512;
        float s, c; sincospif(-(float)t * (1.0f/4096.0f), &s, &c);
        Wt[t] = make_float2(c, s);
    }
    if (tid < 16){ float s, c; sincospif(-(float)tid * (1.0f/128.0f),  &s, &c); w4t[tid] = make_float2(c, s); }
    if (tid < 256){ float s, c; sincospif(-(float)tid * (1.0f/2048.0f), &s, &c); w8t[tid] = make_float2(c, s); }

    // ---- load (AoS natural order) + Pearson moments + min/max ----
    float sx = 0.f, sy = 0.f, sxy = 0.f, sx2 = 0.f, sy2 = 0.f;
    float xmn = INFINITY, xmx = -INFINITY, ymn = INFINITY, ymx = -INFINITY;
    #pragma unroll 4
    for (int it = 0; it < 16; it++){
        int n = tid + it * THREADS;
        float2 a = xr[n], b = yr[n];
        sx  += a.x + a.y;          sy  += b.x + b.y;
        sxy += a.x*b.x + a.y*b.y;
        sx2 += a.x*a.x + a.y*a.y;  sy2 += b.x*b.x + b.y*b.y;
        xmn = fminf(xmn, fminf(a.x, a.y)); xmx = fmaxf(xmx, fmaxf(a.x, a.y));
        ymn = fminf(ymn, fminf(b.x, b.y)); ymx = fmaxf(ymx, fmaxf(b.x, b.y));
        Ap[n] = a; Bp[n] = b;
    }
    sx  = warp_sum(sx);  sy  = warp_sum(sy); sxy = warp_sum(sxy);
    sx2 = warp_sum(sx2); sy2 = warp_sum(sy2);
    #pragma unroll
    for (int o = 16; o; o >>= 1){
        xmn = fminf(xmn, __shfl_down_sync(0xffffffffu, xmn, o));
        xmx = fmaxf(xmx, __shfl_down_sync(0xffffffffu, xmx, o));
        ymn = fminf(ymn, __shfl_down_sync(0xffffffffu, ymn, o));
        ymx = fmaxf(ymx, __shfl_down_sync(0xffffffffu, ymx, o));
    }
    if (lane == 0){
        s_red[warp][0]=sx;  s_red[warp][1]=sy;  s_red[warp][2]=sxy;
        s_red[warp][3]=sx2; s_red[warp][4]=sy2;
        s_red[warp][5]=xmn; s_red[warp][6]=xmx; s_red[warp][7]=ymn; s_red[warp][8]=ymx;
    }
    __syncthreads();
    if (tid == 0){
        double Sx=0,Sy=0,Sxy=0,Sx2=0,Sy2=0;
        float a = s_red[0][5], b = s_red[0][6], c = s_red[0][7], d = s_red[0][8];
        for (int w = 0; w < NWARP; w++){
            Sx+=s_red[w][0]; Sy+=s_red[w][1]; Sxy+=s_red[w][2];
            Sx2+=s_red[w][3]; Sy2+=s_red[w][4];
            a = fminf(a, s_red[w][5]); b = fmaxf(b, s_red[w][6]);
            c = fminf(c, s_red[w][7]); d = fmaxf(d, s_red[w][8]);
        }
        const double N = (double)NFULL;
        r_pear = 1.0 - (N*Sxy - Sx*Sy) / sqrt((N*Sx2 - Sx*Sx) * (N*Sy2 - Sy*Sy));
        s_mm[0]=a; s_mm[1]=b; s_mm[2]=c; s_mm[3]=d;
    }
    __syncthreads();

    // ---- pred FFT pass 1 (A -> C, L=1) with MI histogram fused ----
    {
        const float xmin = s_mm[0], ymin = s_mm[2];
        const float bwx = __fdiv_rn(s_mm[1] - s_mm[0], 10.0f);
        const float bwy = __fdiv_rn(s_mm[3] - s_mm[2], 10.0f);
        int j = tid;
        float2 x[16];
        #pragma unroll
        for (int c = 0; c < 16; c++){
            int n = j + 512*c;
            float2 a = Ap[n];
            float2 b = Bp[n];
            x[c] = a;
            int ix0 = min(max((int)__fdiv_rn(a.x - xmin, bwx), 0), 9);
            int iy0 = min(max((int)__fdiv_rn(b.x - ymin, bwy), 0), 9);
            int ix1 = min(max((int)__fdiv_rn(a.y - xmin, bwx), 0), 9);
            int iy1 = min(max((int)__fdiv_rn(b.y - ymin, bwy), 0), 9);
            atomicAdd(&hist[ix0 * 10 + iy0], 1u);
            atomicAdd(&hist[ix1 * 10 + iy1], 1u);
        }
        fft16<0>(x);
        #pragma unroll
        for (int c = 0; c < 16; c++) Cp[swz1(16*j + c)] = x[c];
    }
    __syncthreads();

    // ---- MI final math on warp 0 (hist stable; other warps proceed) ----
    if (warp == 0){
        const float eps = 1e-8f;
        const float invD = 1.0f / 8388608.0f;   // 1/(B*S), faithful to reference
        if (lane < 10){
            float hx = 0.f, hy = 0.f;
            for (int j = 0; j < 10; j++){
                hx += (float)hist[lane*10 + j];
                hy += (float)hist[j*10 + lane];
            }
            s_hx[lane] = hx; s_hy[lane] = hy;
        }
        __syncwarp();
        float mi = 0.f;
        for (int b = lane; b < 100; b += 32){
            float px  = s_hx[b/10] * invD;
            float py  = s_hy[b%10] * invD;
            float pxy = (float)hist[b] * invD;
            mi += pxy * logf(__fdiv_rn(pxy + eps, px * py + eps));
        }
        mi = warp_sum(mi);
        float he = 0.f;
        if (lane < 10){
            float px = s_hx[lane] * invD, py = s_hy[lane] * invD;
            he = -px * logf(px + eps) - py * logf(py + eps);
        }
        he = warp_sum(he);
        if (lane == 0) r_nmi = (double)(mi / (0.5f * he));
    }

    passR16<4,0,1>(Cp, Ap, w4t); __syncthreads();
    passR16<8,0,0>(Ap, Cp, w8t); __syncthreads();
    pass2<0>(Cp, Ap, Wt);        __syncthreads();   // pred spectrum in A

    // ---- targ forward FFT: B <-> C ----
    pass16p<0>(Bp, Cp);          __syncthreads();
    passR16<4,0,1>(Cp, Bp, w4t); __syncthreads();
    passR16<8,0,0>(Bp, Cp, w8t); __syncthreads();
    pass2<0>(Cp, Bp, Wt);        __syncthreads();   // targ spectrum in B

    // ---- spectra: power-spectrum sums + hann-windowed phase correlation -> C ----
    float accd = 0.f, acct = 0.f;
    float2 lastX0p, lastX0t, lastXpp, lastXpt;
    for (int it = 0; it < 16; it++){
        int k = tid + it * 512;               // 0..8191
        float2 w0 = twget16k<0>(Wt, k);
        float2 X0p = spec_at(Ap, k, w0);
        float2 X0t = spec_at(Bp, k, w0);
        float2 Xmp, Xmt, Xpp, Xpt;
        Xmp.x = __shfl_up_sync(0xffffffffu, X0p.x, 1);
        Xmp.y = __shfl_up_sync(0xffffffffu, X0p.y, 1);
        Xmt.x = __shfl_up_sync(0xffffffffu, X0t.x, 1);
        Xmt.y = __shfl_up_sync(0xffffffffu, X0t.y, 1);
        Xpp.x = __shfl_down_sync(0xffffffffu, X0p.x, 1);
        Xpp.y = __shfl_down_sync(0xffffffffu, X0p.y, 1);
        Xpt.x = __shfl_down_sync(0xffffffffu, X0t.x, 1);
        Xpt.y = __shfl_down_sync(0xffffffffu, X0t.y, 1);
        if (lane == 0){
            if (k == 0){
                float2 w1 = twget16k<0>(Wt, 1);
                Xmp = cconj(spec_at(Ap, 1, w1));   // X[-1] = conj(X[1])
                Xmt = cconj(spec_at(Bp, 1, w1));
            } else {
                float2 wm = twget16k<0>(Wt, k-1);
                Xmp = spec_at(Ap, k-1, wm);
                Xmt = spec_at(Bp, k-1, wm);
            }
        }
        if (lane == 31){
            float2 wp = twget16k<0>(Wt, k+1);
            Xpp = spec_at(Ap, k+1, wp);
            Xpt = spec_at(Bp, k+1, wp);
        }
        float pp = X0p.x*X0p.x + X0p.y*X0p.y;
        float pt = X0t.x*X0t.x + X0t.y*X0t.y;
        accd += fabsf(pp - pt);
        acct += pt;
        float2 xf = make_float2(0.5f*X0p.x - 0.25f*(Xmp.x + Xpp.x),
                                0.5f*X0p.y - 0.25f*(Xmp.y + Xpp.y));
        float2 tf = make_float2(0.5f*X0t.x - 0.25f*(Xmt.x + Xpt.x),
                                0.5f*X0t.y - 0.25f*(Xmt.y + Xpt.y));
        float2 c = cmul(xf, cconj(tf));
        float inv = rsqrtf(c.x*c.x + c.y*c.y);
        Cp[k] = make_float2(c.x * inv, c.y * inv);
        lastX0p = X0p; lastX0t = X0t; lastXpp = Xpp; lastXpt = Xpt;
    }
    if (tid == THREADS - 1){
        // bin 8192: X0' = X[8192] (= lastXpp), Xm' = X[8191], Xp' = conj(X[8191])
        float2 X0p = lastXpp, X0t = lastXpt;
        float2 Xmp = lastX0p, Xmt = lastX0t;
        float2 Xpp = cconj(Xmp), Xpt = cconj(Xmt);
        float pp = X0p.x*X0p.x + X0p.y*X0p.y;
        float pt = X0t.x*X0t.x + X0t.y*X0t.y;
        accd += fabsf(pp - pt);
        acct += pt;
        float2 xf = make_float2(0.5f*X0p.x - 0.25f*(Xmp.x + Xpp.x),
                                0.5f*X0p.y - 0.25f*(Xmp.y + Xpp.y));
        float2 tf = make_float2(0.5f*X0t.x - 0.25f*(Xmt.x + Xpt.x),
                                0.5f*X0t.y - 0.25f*(Xmt.y + Xpt.y));
        float2 c = cmul(xf, cconj(tf));
        float inv = rsqrtf(c.x*c.x + c.y*c.y);
        s_c8192 = make_float2(c.x * inv, c.y * inv);
    }
    accd = warp_sum(accd); acct = warp_sum(acct);
    if (lane == 0){ s_red[warp][0] = accd; s_red[warp][1] = acct; }
    __syncthreads();
    if (tid == 0){
        double d = 0.0, t2 = 0.0;
        for (int w = 0; w < NWARP; w++){ d += s_red[w][0]; t2 += s_red[w][1]; }
        r_absd = d; r_tp = t2;
    }

    // ---- inverse pass 1 with spectrum-pack folded in: C -> A (swz1 writes) ----
    {
        int j = tid;
        float2 x[16];
        #pragma unroll
        for (int c = 0; c < 16; c++){
            int n = j + 512*c;
            float2 Bn = Cp[n];
            float2 Bm = (n == 0) ? s_c8192 : cconj(Cp[8192 - n]);  // conj(C[8192-n])
            float2 E = make_float2(0.5f*(Bn.x + Bm.x), 0.5f*(Bn.y + Bm.y));
            float2 D = make_float2(0.5f*(Bn.x - Bm.x), 0.5f*(Bn.y - Bm.y));
            float2 wn = twget16k<1>(Wt, n);          // e^{+i pi n/8192}
            float2 O  = cmul(wn, D);
            x[c] = make_float2(E.x - O.y, E.y + O.x);  // E + i*O
        }
        fft16<1>(x);
        #pragma unroll
        for (int c = 0; c < 16; c++) Ap[swz1(16*j + c)] = x[c];
    }
    __syncthreads();

    passR16<4,1,1>(Ap, Cp, w4t); __syncthreads();
    passR16<8,1,0>(Cp, Ap, w8t); __syncthreads();   // inverse penultimate in A

    // ---- argmax with final radix-2 pass folded in (first-occurrence tie break) ----
    float best = -INFINITY; int bi = 0x7fffffff;
    #pragma unroll 2
    for (int it = 0; it < 8; it++){
        int jj = tid + it * 512;              // 0..4095
        float2 u = Ap[jj];
        float2 v = Ap[jj + 4096];
        float2 wv = cmul(v, twget<1>(Wt, jj));
        float y0r = u.x + wv.x, y0i = u.y + wv.y;   // Z[jj]      -> times 2jj, 2jj+1
        float y1r = u.x - wv.x, y1i = u.y - wv.y;   // Z[jj+4096] -> times 2jj+8192, +8193
        int e0 = 2*jj, o0 = 2*jj + 1, e1 = 2*jj + 8192, o1 = 2*jj + 8193;
        if (y0r > best || (y0r == best && e0 < bi)){ best = y0r; bi = e0; }
        if (y0i > best || (y0i == best && o0 < bi)){ best = y0i; bi = o0; }
        if (y1r > best || (y1r == best && e1 < bi)){ best = y1r; bi = e1; }
        if (y1i > best || (y1i == best && o1 < bi)){ best = y1i; bi = o1; }
    }
    #pragma unroll
    for (int off = 16; off; off >>= 1){
        float ov = __shfl_down_sync(0xffffffffu, best, off);
        int   oi = __shfl_down_sync(0xffffffffu, bi,   off);
        if (ov > best || (ov == best && oi < bi)){ best = ov; bi = oi; }
    }
    if (lane == 0){ s_red[warp][0] = best; s_idx[warp] = bi; }
    __syncthreads();
    if (tid == 0){
        best = s_red[0][0]; bi = s_idx[0];
        for (int w = 1; w < NWARP; w++){
            float v = s_red[w][0]; int ix = s_idx[w];
            if (v > best || (v == best && ix < bi)){ best = v; bi = ix; }
        }
        r_cos = (double)cosf(2.0f * (float)PI_D * (float)bi / 16384.0f);

        // publish this row's results (release), then arrive
        g_row[row].pear = r_pear;
        g_row[row].cosv = r_cos;
        g_row[row].absd = r_absd;
        g_row[row].tp   = r_tp;
        g_row[row].nmi  = r_nmi;
        __threadfence();
        unsigned prev = atomicAdd(&g_done, 1u);
        s_last = ((prev % ROWS) == ROWS - 1) ? 1u : 0u;
        if (s_last) __threadfence();   // acquire: order g_row reads after counter observation
    }
    __syncthreads();

    // ---- last CTA reduces all rows and writes the scalar loss ----
    if (s_last){
        double pe = 0.0, co = 0.0, ad = 0.0, tp = 0.0, nm = 0.0;
        for (int r = tid; r < ROWS; r += THREADS){
            const double* p = (const double*)&g_row[r];
            pe += __ldcg(p + 0);
            co += __ldcg(p + 1);
            ad += __ldcg(p + 2);
            tp += __ldcg(p + 3);
            nm += __ldcg(p + 4);
        }
        pe = warp_sum_d(pe); co = warp_sum_d(co); ad = warp_sum_d(ad);
        tp = warp_sum_d(tp); nm = warp_sum_d(nm);
        if (lane == 0){
            s_fin[warp][0]=pe; s_fin[warp][1]=co; s_fin[warp][2]=ad;
            s_fin[warp][3]=tp; s_fin[warp][4]=nm;
        }
        __syncthreads();
        if (tid == 0){
            double Pe=0, Co=0, Ad=0, Tp=0, Nm=0;
            for (int w = 0; w < NWARP; w++){
                Pe+=s_fin[w][0]; Co+=s_fin[w][1]; Ad+=s_fin[w][2];
                Tp+=s_fin[w][3]; Nm+=s_fin[w][4];
            }
            int ep = *pep;
            double loss = Pe / (double)ROWS;
            if (ep >= 400){
                loss += 1.0 - Co / (double)ROWS;   // phase correlation
                loss += Ad / Tp;                   // power spectrum
            }
            if (ep >= 700){
                loss += 1.0 - Nm / (double)ROWS;   // mutual information
            }
            out[0] = (float)loss;
        }
    }
}

// ---------------- launch ----------------
extern "C" void kernel_launch(void* const* d_in, const int* in_sizes, int n_in,
                              void* d_out, int out_size){
    const float* pred = (const float*)d_in[0];
    const float* targ = (const float*)d_in[1];
    const int*   pi   = (const int*)d_in[2];
    const int*   pep  = (const int*)d_in[3];
    float* out = (float*)d_out;

    // 3 planes of 8192 float2 + (2048+16+256) float2 twiddles = 215168 bytes
    const size_t smem_bytes = (size_t)(24576 + 2048 + 16 + 256) * sizeof(float2);
    cudaFuncSetAttribute(row_kernel, cudaFuncAttributeMaxDynamicSharedMemorySize,
                         (int)smem_bytes);

    row_kernel<<<ROWS, THREADS, smem_bytes>>>(pred, targ, pi, pep, out);
}

// round 13
// speedup vs baseline: 1.4558x; 1.0274x over previous
#include <cuda_runtime.h>
#include <math.h>
#include <stdint.h>

#define THREADS 512
#define NWARP 16
#define M 8192            // packed complex FFT size
#define NFULL 16384       // real signal length
#define ROWS 512
#define PI_D 3.14159265358979323846

// e^{-i pi/8192} (for W_16384 odd-index fixup)
#define K16C 0.99999992646571785f
#define K16S 0.00038349518757139556f

// ---------------- per-row outputs + completion counter (no allocation) --------
struct RowOut { double pear, cosv, absd, tp, nmi; };
__device__ RowOut  g_row[ROWS];
__device__ unsigned g_done = 0;    // monotonic across launches; (prev % ROWS) picks finalizer

// ---------------- packed f32x2 helpers (sm_103a: only reachable via PTX) ------
__device__ __forceinline__ unsigned long long pk(float2 a){
    unsigned long long u;
    asm("mov.b64 %0, {%1,%2};" : "=l"(u) : "f"(a.x), "f"(a.y));
    return u;
}
__device__ __forceinline__ float2 upk(unsigned long long u){
    float2 r;
    asm("mov.b64 {%0,%1}, %2;" : "=f"(r.x), "=f"(r.y) : "l"(u));
    return r;
}
__device__ __forceinline__ float2 cadd(float2 a, float2 b){
    unsigned long long r, ua = pk(a), ub = pk(b);
    asm("add.rn.f32x2 %0, %1, %2;" : "=l"(r) : "l"(ua), "l"(ub));
    return upk(r);
}
__device__ __forceinline__ float2 csub(float2 a, float2 b){
    unsigned long long r, ua = pk(a), ub = pk(b);
    asm("sub.rn.f32x2 %0, %1, %2;" : "=l"(r) : "l"(ua), "l"(ub));
    return upk(r);
}
// lanewise a*m + c
__device__ __forceinline__ float2 cfma2(float2 a, unsigned long long m, float2 c){
    unsigned long long r, ua = pk(a), uc = pk(c);
    asm("fma.rn.f32x2 %0, %1, %2, %3;" : "=l"(r) : "l"(ua), "l"(m), "l"(uc));
    return upk(r);
}

// ---------------- complex helpers ----------------
__device__ __forceinline__ float2 cmul(float2 a, float2 b){
    return make_float2(a.x*b.x - a.y*b.y, a.x*b.y + a.y*b.x);
}
__device__ __forceinline__ float2 cconj(float2 a){ return make_float2(a.x, -a.y); }

__device__ __forceinline__ float warp_sum(float v){
    #pragma unroll
    for (int o = 16; o; o >>= 1) v += __shfl_down_sync(0xffffffffu, v, o);
    return v;
}
__device__ __forceinline__ double warp_sum_d(double v){
    #pragma unroll
    for (int o = 16; o; o >>= 1) v += __shfl_down_sync(0xffffffffu, v, o);
    return v;
}

// ---------------- table twiddle fetch ----------------
// W_8192^k = e^{-2 pi i k / 8192}, k in [0, 8192); table holds k < 2048
template<int INV>
__device__ __forceinline__ float2 twget(const float2* __restrict__ Wt, int k){
    float2 w = Wt[k & 2047];
    int q = (k >> 11) & 3;
    float2 r = w;
    if (q == 1) r = make_float2( w.y, -w.x);
    else if (q == 2) r = make_float2(-w.x, -w.y);
    else if (q == 3) r = make_float2(-w.y,  w.x);
    if (INV) r.y = -r.y;
    return r;
}
// W_16384^k = e^{-i pi k / 8192}, k in [0, 8192]
template<int INV>
__device__ __forceinline__ float2 twget16k(const float2* __restrict__ Wt, int k){
    float2 w = twget<0>(Wt, k >> 1);
    if (k & 1) w = cmul(w, make_float2(K16C, -K16S));
    if (INV) w.y = -w.y;
    return w;
}

template<int INV>
__device__ __forceinline__ float2 cmulK(float2 a, float wr, float wi){
    float i2 = INV ? -wi : wi;
    return make_float2(a.x*wr - a.y*i2, a.x*i2 + a.y*wr);
}

// radix-4 DIT butterfly (natural-order DFT4), packed-add form.
// Forward: o1 = (d.x+d2.y, d.y-d2.x), o3 = (d.x-d2.y, d.y+d2.x); inverse swaps.
template<int INV>
__device__ __forceinline__ void bfly4(float2 b0, float2 b1, float2 b2, float2 b3,
                                      float2& o0, float2& o1, float2& o2, float2& o3){
    const unsigned long long CPM = pk(make_float2( 1.f, -1.f));
    const unsigned long long CMP = pk(make_float2(-1.f,  1.f));
    float2 s  = cadd(b0, b2), d  = csub(b0, b2);
    float2 s2 = cadd(b1, b3), d2 = csub(b1, b3);
    o0 = cadd(s, s2); o2 = csub(s, s2);
    float2 d2s = make_float2(d2.y, d2.x);
    if (!INV){ o1 = cfma2(d2s, CPM, d); o3 = cfma2(d2s, CMP, d); }
    else     { o1 = cfma2(d2s, CMP, d); o3 = cfma2(d2s, CPM, d); }
}

// 16-point FFT in registers, natural in/out (two radix-4 micro-passes)
template<int INV>
__device__ __forceinline__ void fft16(float2* x){
    float2 t[16];
    #pragma unroll
    for (int g = 0; g < 4; g++)
        bfly4<INV>(x[g], x[g+4], x[g+8], x[g+12], t[4*g], t[4*g+1], t[4*g+2], t[4*g+3]);
    const float C1 = 0.9238795325112867f, S1 = 0.3826834323650898f, R2 = 0.7071067811865476f;
    bfly4<INV>(t[0], t[4], t[8], t[12], x[0], x[4], x[8], x[12]);
    bfly4<INV>(t[1], cmulK<INV>(t[5],  C1, -S1), cmulK<INV>(t[9],  R2, -R2), cmulK<INV>(t[13],  S1, -C1),
               x[1], x[5], x[9], x[13]);
    bfly4<INV>(t[2], cmulK<INV>(t[6],  R2, -R2), cmulK<INV>(t[10], 0.f, -1.f), cmulK<INV>(t[14], -R2, -R2),
               x[2], x[6], x[10], x[14]);
    bfly4<INV>(t[3], cmulK<INV>(t[7],  S1, -C1), cmulK<INV>(t[11], -R2, -R2), cmulK<INV>(t[15], -C1,  S1),
               x[3], x[7], x[11], x[15]);
}

// ---------------- element swizzle (AoS float2 planes) ----------------
__device__ __forceinline__ int swz1(int a){ return a ^ ((a >> 4) & 31); }

// Stockham radix-16 pass, L=1 (twiddle-free), natural reads, swz1 writes
template<int INV>
__device__ __forceinline__ void pass16p(const float2* __restrict__ zi, float2* __restrict__ zo){
    int j = threadIdx.x;
    float2 x[16];
    #pragma unroll
    for (int c = 0; c < 16; c++) x[c] = zi[j + 512*c];
    fft16<INV>(x);
    #pragma unroll
    for (int c = 0; c < 16; c++) zo[swz1(16*j + c)] = x[c];
}

// Stockham radix-16 pass at sub-length L = 2^LOG2L (L in {16, 256}), w1 from tiny table.
template<int LOG2L, int INV, int SWR>
__device__ __forceinline__ void passR16(const float2* __restrict__ zi, float2* __restrict__ zo,
                                        const float2* __restrict__ wtab){
    const int L = 1 << LOG2L;
    int j = threadIdx.x;
    int r = j & (L - 1);
    int s = j >> LOG2L;
    float2 x[16];
    #pragma unroll
    for (int m = 0; m < 16; m++){
        int a = j + 512*m;
        if (SWR) a = swz1(a);
        x[m] = zi[a];
    }
    float2 w1 = wtab[r];
    if (INV) w1.y = -w1.y;
    float2 w2 = cmul(w1, w1);
    float2 w3 = cmul(w2, w1);
    float2 w4 = cmul(w2, w2);
    float2 w8 = cmul(w4, w4);
    x[1]  = cmul(x[1],  w1);
    x[2]  = cmul(x[2],  w2);
    x[3]  = cmul(x[3],  w3);
    x[4]  = cmul(x[4],  w4);
    x[5]  = cmul(x[5],  cmul(w4, w1));
    x[6]  = cmul(x[6],  cmul(w4, w2));
    x[7]  = cmul(x[7],  cmul(w4, w3));
    x[8]  = cmul(x[8],  w8);
    x[9]  = cmul(x[9],  cmul(w8, w1));
    x[10] = cmul(x[10], cmul(w8, w2));
    x[11] = cmul(x[11], cmul(w8, w3));
    x[12] = cmul(x[12], cmul(w8, w4));
    x[13] = cmul(x[13], cmul(w8, cmul(w4, w1)));
    x[14] = cmul(x[14], cmul(w8, cmul(w4, w2)));
    x[15] = cmul(x[15], cmul(w8, cmul(w4, w3)));
    fft16<INV>(x);
    int base = r + (s << (LOG2L + 4));
    #pragma unroll
    for (int c = 0; c < 16; c++)
        zo[base + (c << LOG2L)] = x[c];
}

// final Stockham radix-2 pass (L=4096), forward chains only
template<int INV>
__device__ __forceinline__ void pass2(const float2* __restrict__ zi, float2* __restrict__ zo,
                                      const float2* __restrict__ Wt){
    #pragma unroll
    for (int it = 0; it < 8; it++){
        int j = threadIdx.x + it * 512;
        float2 a = zi[j];
        float2 v = cmul(zi[j + 4096], twget<INV>(Wt, j));
        zo[j]        = cadd(a, v);
        zo[j + 4096] = csub(a, v);
    }
}

// returns 2*X[k] of the length-16384 real signal (uniform exact scale; all
// consumers — power-spectrum ratio, normalized phase corr, argmax — invariant)
__device__ __forceinline__ float2 spec_at(const float2* __restrict__ Z, int k, float2 w){
    float2 a = Z[k & (M - 1)];
    float2 b = Z[(M - k) & (M - 1)];
    float2 E = make_float2(a.x + b.x, a.y - b.y);
    float2 O = make_float2(a.y + b.y, b.x - a.x);
    return cadd(E, cmul(w, O));
}

// ---------------- single fused kernel: one CTA per row, last CTA finalizes ----
__global__ __launch_bounds__(THREADS, 1)
void row_kernel(const float* __restrict__ pred, const float* __restrict__ targ,
                const int* __restrict__ pi, const int* __restrict__ pep,
                float* __restrict__ out){
    extern __shared__ float2 smz[];
    float2* Ap = smz;               // 8192
    float2* Bp = smz + 8192;        // 8192
    float2* Cp = smz + 16384;       // 8192
    float2* Wt  = smz + 24576;      // 2048: W_8192^k, k<2048
    float2* w4t = smz + 26624;      // 16:   e^{-i pi r/128}
    float2* w8t = smz + 26640;      // 256:  e^{-i pi r/2048}

    __shared__ float    s_red[NWARP][10];
    __shared__ int      s_idx[NWARP];
    __shared__ float    s_mm[4];
    __shared__ unsigned hist[100];
    __shared__ float    s_hx[10], s_hy[10];
    __shared__ float2   s_c8192;
    __shared__ unsigned s_last;
    __shared__ double   s_fin[NWARP][5];

    const int tid  = threadIdx.x;
    const int warp = tid >> 5, lane = tid & 31;
    const int row  = blockIdx.x;
    const int i0   = *pi;

    double r_pear = 0.0, r_cos = 0.0, r_absd = 0.0, r_tp = 0.0, r_nmi = 0.0;

    const float2* xr = (const float2*)(pred + ((size_t)i0 * ROWS + row) * (size_t)NFULL);
    const float2* yr = (const float2*)(targ + (size_t)row * (size_t)NFULL);

    if (tid < 100) hist[tid] = 0u;

    // ---- one-time twiddle tables (accurate sincospif; ~5 calls/thread) ----
    #pragma unroll
    for (int it = 0; it < 4; it++){
        int t = tid + it * 512;
        float s, c; sincospif(-(float)t * (1.0f/4096.0f), &s, &c);
        Wt[t] = make_float2(c, s);
    }
    if (tid < 16){ float s, c; sincospif(-(float)tid * (1.0f/128.0f),  &s, &c); w4t[tid] = make_float2(c, s); }
    if (tid < 256){ float s, c; sincospif(-(float)tid * (1.0f/2048.0f), &s, &c); w8t[tid] = make_float2(c, s); }

    // ---- load (AoS natural order) + Pearson moments + min/max ----
    float sx = 0.f, sy = 0.f, sxy = 0.f, sx2 = 0.f, sy2 = 0.f;
    float xmn = INFINITY, xmx = -INFINITY, ymn = INFINITY, ymx = -INFINITY;
    #pragma unroll 4
    for (int it = 0; it < 16; it++){
        int n = tid + it * THREADS;
        float2 a = xr[n], b = yr[n];
        sx  += a.x + a.y;          sy  += b.x + b.y;
        sxy += a.x*b.x + a.y*b.y;
        sx2 += a.x*a.x + a.y*a.y;  sy2 += b.x*b.x + b.y*b.y;
        xmn = fminf(xmn, fminf(a.x, a.y)); xmx = fmaxf(xmx, fmaxf(a.x, a.y));
        ymn = fminf(ymn, fminf(b.x, b.y)); ymx = fmaxf(ymx, fmaxf(b.x, b.y));
        Ap[n] = a; Bp[n] = b;
    }
    sx  = warp_sum(sx);  sy  = warp_sum(sy); sxy = warp_sum(sxy);
    sx2 = warp_sum(sx2); sy2 = warp_sum(sy2);
    #pragma unroll
    for (int o = 16; o; o >>= 1){
        xmn = fminf(xmn, __shfl_down_sync(0xffffffffu, xmn, o));
        xmx = fmaxf(xmx, __shfl_down_sync(0xffffffffu, xmx, o));
        ymn = fminf(ymn, __shfl_down_sync(0xffffffffu, ymn, o));
        ymx = fmaxf(ymx, __shfl_down_sync(0xffffffffu, ymx, o));
    }
    if (lane == 0){
        s_red[warp][0]=sx;  s_red[warp][1]=sy;  s_red[warp][2]=sxy;
        s_red[warp][3]=sx2; s_red[warp][4]=sy2;
        s_red[warp][5]=xmn; s_red[warp][6]=xmx; s_red[warp][7]=ymn; s_red[warp][8]=ymx;
    }
    __syncthreads();
    if (tid == 0){
        double Sx=0,Sy=0,Sxy=0,Sx2=0,Sy2=0;
        float a = s_red[0][5], b = s_red[0][6], c = s_red[0][7], d = s_red[0][8];
        for (int w = 0; w < NWARP; w++){
            Sx+=s_red[w][0]; Sy+=s_red[w][1]; Sxy+=s_red[w][2];
            Sx2+=s_red[w][3]; Sy2+=s_red[w][4];
            a = fminf(a, s_red[w][5]); b = fmaxf(b, s_red[w][6]);
            c = fminf(c, s_red[w][7]); d = fmaxf(d, s_red[w][8]);
        }
        const double N = (double)NFULL;
        r_pear = 1.0 - (N*Sxy - Sx*Sy) / sqrt((N*Sx2 - Sx*Sx) * (N*Sy2 - Sy*Sy));
        s_mm[0]=a; s_mm[1]=b; s_mm[2]=c; s_mm[3]=d;
    }
    __syncthreads();

    // ---- pred FFT pass 1 (A -> C, L=1) with MI histogram fused ----
    {
        const float xmin = s_mm[0], ymin = s_mm[2];
        const float bwx = __fdiv_rn(s_mm[1] - s_mm[0], 10.0f);
        const float bwy = __fdiv_rn(s_mm[3] - s_mm[2], 10.0f);
        int j = tid;
        float2 x[16];
        #pragma unroll
        for (int c = 0; c < 16; c++){
            int n = j + 512*c;
            float2 a = Ap[n];
            float2 b = Bp[n];
            x[c] = a;
            int ix0 = min(max((int)__fdiv_rn(a.x - xmin, bwx), 0), 9);
            int iy0 = min(max((int)__fdiv_rn(b.x - ymin, bwy), 0), 9);
            int ix1 = min(max((int)__fdiv_rn(a.y - xmin, bwx), 0), 9);
            int iy1 = min(max((int)__fdiv_rn(b.y - ymin, bwy), 0), 9);
            atomicAdd(&hist[ix0 * 10 + iy0], 1u);
            atomicAdd(&hist[ix1 * 10 + iy1], 1u);
        }
        fft16<0>(x);
        #pragma unroll
        for (int c = 0; c < 16; c++) Cp[swz1(16*j + c)] = x[c];
    }
    __syncthreads();

    // ---- MI final math on warp 0 (hist stable; other warps proceed) ----
    if (warp == 0){
        const float eps = 1e-8f;
        const float invD = 1.0f / 8388608.0f;   // 1/(B*S), faithful to reference
        if (lane < 10){
            float hx = 0.f, hy = 0.f;
            for (int j = 0; j < 10; j++){
                hx += (float)hist[lane*10 + j];
                hy += (float)hist[j*10 + lane];
            }
            s_hx[lane] = hx; s_hy[lane] = hy;
        }
        __syncwarp();
        float mi = 0.f;
        for (int b = lane; b < 100; b += 32){
            float px  = s_hx[b/10] * invD;
            float py  = s_hy[b%10] * invD;
            float pxy = (float)hist[b] * invD;
            mi += pxy * logf(__fdiv_rn(pxy + eps, px * py + eps));
        }
        mi = warp_sum(mi);
        float he = 0.f;
        if (lane < 10){
            float px = s_hx[lane] * invD, py = s_hy[lane] * invD;
            he = -px * logf(px + eps) - py * logf(py + eps);
        }
        he = warp_sum(he);
        if (lane == 0) r_nmi = (double)(mi / (0.5f * he));
    }

    passR16<4,0,1>(Cp, Ap, w4t); __syncthreads();
    passR16<8,0,0>(Ap, Cp, w8t); __syncthreads();
    pass2<0>(Cp, Ap, Wt);        __syncthreads();   // pred spectrum in A

    // ---- targ forward FFT: B <-> C ----
    pass16p<0>(Bp, Cp);          __syncthreads();
    passR16<4,0,1>(Cp, Bp, w4t); __syncthreads();
    passR16<8,0,0>(Bp, Cp, w8t); __syncthreads();
    pass2<0>(Cp, Bp, Wt);        __syncthreads();   // targ spectrum in B

    // ---- spectra: power-spectrum sums + hann-windowed phase correlation -> C ----
    // All quantities carry uniform exact power-of-2 scales (see spec_at); the
    // ratio r_absd/r_tp and the normalized correlation are bit-invariant.
    float accd = 0.f, acct = 0.f;
    float2 lastX0p, lastX0t, lastXpp, lastXpt;
    for (int it = 0; it < 16; it++){
        int k = tid + it * 512;               // 0..8191
        float2 w0 = twget16k<0>(Wt, k);
        float2 X0p = spec_at(Ap, k, w0);
        float2 X0t = spec_at(Bp, k, w0);
        float2 Xmp, Xmt, Xpp, Xpt;
        Xmp.x = __shfl_up_sync(0xffffffffu, X0p.x, 1);
        Xmp.y = __shfl_up_sync(0xffffffffu, X0p.y, 1);
        Xmt.x = __shfl_up_sync(0xffffffffu, X0t.x, 1);
        Xmt.y = __shfl_up_sync(0xffffffffu, X0t.y, 1);
        Xpp.x = __shfl_down_sync(0xffffffffu, X0p.x, 1);
        Xpp.y = __shfl_down_sync(0xffffffffu, X0p.y, 1);
        Xpt.x = __shfl_down_sync(0xffffffffu, X0t.x, 1);
        Xpt.y = __shfl_down_sync(0xffffffffu, X0t.y, 1);
        if (lane == 0){
            if (k == 0){
                float2 w1 = twget16k<0>(Wt, 1);
                Xmp = cconj(spec_at(Ap, 1, w1));   // X[-1] = conj(X[1])
                Xmt = cconj(spec_at(Bp, 1, w1));
            } else {
                float2 wm = twget16k<0>(Wt, k-1);
                Xmp = spec_at(Ap, k-1, wm);
                Xmt = spec_at(Bp, k-1, wm);
            }
        }
        if (lane == 31){
            float2 wp = twget16k<0>(Wt, k+1);
            Xpp = spec_at(Ap, k+1, wp);
            Xpt = spec_at(Bp, k+1, wp);
        }
        float pp = X0p.x*X0p.x + X0p.y*X0p.y;
        float pt = X0t.x*X0t.x + X0t.y*X0t.y;
        accd += fabsf(pp - pt);
        acct += pt;
        // hann in frequency, scale-stripped: xf = 2*X0 - (Xm + Xp)
        float2 xf = csub(cadd(X0p, X0p), cadd(Xmp, Xpp));
        float2 tf = csub(cadd(X0t, X0t), cadd(Xmt, Xpt));
        float2 c = cmul(xf, cconj(tf));
        float inv = rsqrtf(c.x*c.x + c.y*c.y);
        Cp[k] = make_float2(c.x * inv, c.y * inv);
        lastX0p = X0p; lastX0t = X0t; lastXpp = Xpp; lastXpt = Xpt;
    }
    if (tid == THREADS - 1){
        // bin 8192: X0' = X[8192] (= lastXpp), Xm' = X[8191], Xp' = conj(X[8191])
        float2 X0p = lastXpp, X0t = lastXpt;
        float2 Xmp = lastX0p, Xmt = lastX0t;
        float2 Xpp = cconj(Xmp), Xpt = cconj(Xmt);
        float pp = X0p.x*X0p.x + X0p.y*X0p.y;
        float pt = X0t.x*X0t.x + X0t.y*X0t.y;
        accd += fabsf(pp - pt);
        acct += pt;
        float2 xf = csub(cadd(X0p, X0p), cadd(Xmp, Xpp));
        float2 tf = csub(cadd(X0t, X0t), cadd(Xmt, Xpt));
        float2 c = cmul(xf, cconj(tf));
        float inv = rsqrtf(c.x*c.x + c.y*c.y);
        s_c8192 = make_float2(c.x * inv, c.y * inv);
    }
    accd = warp_sum(accd); acct = warp_sum(acct);
    if (lane == 0){ s_red[warp][0] = accd; s_red[warp][1] = acct; }
    __syncthreads();
    if (tid == 0){
        double d = 0.0, t2 = 0.0;
        for (int w = 0; w < NWARP; w++){ d += s_red[w][0]; t2 += s_red[w][1]; }
        r_absd = d; r_tp = t2;
    }

    // ---- inverse pass 1 with spectrum-pack folded in: C -> A (swz1 writes) ----
    // scale-stripped (x2): inverse output scale is argmax-invariant
    {
        int j = tid;
        float2 x[16];
        #pragma unroll
        for (int c = 0; c < 16; c++){
            int n = j + 512*c;
            float2 Bn = Cp[n];
            float2 Bm = (n == 0) ? s_c8192 : cconj(Cp[8192 - n]);  // conj(C[8192-n])
            float2 E = cadd(Bn, Bm);
            float2 D = csub(Bn, Bm);
            float2 wn = twget16k<1>(Wt, n);          // e^{+i pi n/8192}
            float2 O  = cmul(wn, D);
            x[c] = make_float2(E.x - O.y, E.y + O.x);  // E + i*O
        }
        fft16<1>(x);
        #pragma unroll
        for (int c = 0; c < 16; c++) Ap[swz1(16*j + c)] = x[c];
    }
    __syncthreads();

    passR16<4,1,1>(Ap, Cp, w4t); __syncthreads();
    passR16<8,1,0>(Cp, Ap, w8t); __syncthreads();   // inverse penultimate in A

    // ---- argmax with final radix-2 pass folded in (first-occurrence tie break) ----
    float best = -INFINITY; int bi = 0x7fffffff;
    #pragma unroll 2
    for (int it = 0; it < 8; it++){
        int jj = tid + it * 512;              // 0..4095
        float2 u = Ap[jj];
        float2 v = Ap[jj + 4096];
        float2 wv = cmul(v, twget<1>(Wt, jj));
        float y0r = u.x + wv.x, y0i = u.y + wv.y;   // Z[jj]      -> times 2jj, 2jj+1
        float y1r = u.x - wv.x, y1i = u.y - wv.y;   // Z[jj+4096] -> times 2jj+8192, +8193
        int e0 = 2*jj, o0 = 2*jj + 1, e1 = 2*jj + 8192, o1 = 2*jj + 8193;
        if (y0r > best || (y0r == best && e0 < bi)){ best = y0r; bi = e0; }
        if (y0i > best || (y0i == best && o0 < bi)){ best = y0i; bi = o0; }
        if (y1r > best || (y1r == best && e1 < bi)){ best = y1r; bi = e1; }
        if (y1i > best || (y1i == best && o1 < bi)){ best = y1i; bi = o1; }
    }
    #pragma unroll
    for (int off = 16; off; off >>= 1){
        float ov = __shfl_down_sync(0xffffffffu, best, off);
        int   oi = __shfl_down_sync(0xffffffffu, bi,   off);
        if (ov > best || (ov == best && oi < bi)){ best = ov; bi = oi; }
    }
    if (lane == 0){ s_red[warp][0] = best; s_idx[warp] = bi; }
    __syncthreads();
    if (tid == 0){
        best = s_red[0][0]; bi = s_idx[0];
        for (int w = 1; w < NWARP; w++){
            float v = s_red[w][0]; int ix = s_idx[w];
            if (v > best || (v == best && ix < bi)){ best = v; bi = ix; }
        }
        r_cos = (double)cosf(2.0f * (float)PI_D * (float)bi / 16384.0f);

        // publish this row's results (release), then arrive
        g_row[row].pear = r_pear;
        g_row[row].cosv = r_cos;
        g_row[row].absd = r_absd;
        g_row[row].tp   = r_tp;
        g_row[row].nmi  = r_nmi;
        __threadfence();
        unsigned prev = atomicAdd(&g_done, 1u);
        s_last = ((prev % ROWS) == ROWS - 1) ? 1u : 0u;
        if (s_last) __threadfence();   // acquire: order g_row reads after counter observation
    }
    __syncthreads();

    // ---- last CTA reduces all rows and writes the scalar loss ----
    if (s_last){
        double pe = 0.0, co = 0.0, ad = 0.0, tp = 0.0, nm = 0.0;
        for (int r = tid; r < ROWS; r += THREADS){
            const double* p = (const double*)&g_row[r];
            pe += __ldcg(p + 0);
            co += __ldcg(p + 1);
            ad += __ldcg(p + 2);
            tp += __ldcg(p + 3);
            nm += __ldcg(p + 4);
        }
        pe = warp_sum_d(pe); co = warp_sum_d(co); ad = warp_sum_d(ad);
        tp = warp_sum_d(tp); nm = warp_sum_d(nm);
        if (lane == 0){
            s_fin[warp][0]=pe; s_fin[warp][1]=co; s_fin[warp][2]=ad;
            s_fin[warp][3]=tp; s_fin[warp][4]=nm;
        }
        __syncthreads();
        if (tid == 0){
            double Pe=0, Co=0, Ad=0, Tp=0, Nm=0;
            for (int w = 0; w < NWARP; w++){
                Pe+=s_fin[w][0]; Co+=s_fin[w][1]; Ad+=s_fin[w][2];
                Tp+=s_fin[w][3]; Nm+=s_fin[w][4];
            }
            int ep = *pep;
            double loss = Pe / (double)ROWS;
            if (ep >= 400){
                loss += 1.0 - Co / (double)ROWS;   // phase correlation
                loss += Ad / Tp;                   // power spectrum
            }
            if (ep >= 700){
                loss += 1.0 - Nm / (double)ROWS;   // mutual information
            }
            out[0] = (float)loss;
        }
    }
}

// ---------------- launch ----------------
extern "C" void kernel_launch(void* const* d_in, const int* in_sizes, int n_in,
                              void* d_out, int out_size){
    const float* pred = (const float*)d_in[0];
    const float* targ = (const float*)d_in[1];
    const int*   pi   = (const int*)d_in[2];
    const int*   pep  = (const int*)d_in[3];
    float* out = (float*)d_out;

    // 3 planes of 8192 float2 + (2048+16+256) float2 twiddles = 215168 bytes
    const size_t smem_bytes = (size_t)(24576 + 2048 + 16 + 256) * sizeof(float2);
    cudaFuncSetAttribute(row_kernel, cudaFuncAttributeMaxDynamicSharedMemorySize,
                         (int)smem_bytes);

    row_kernel<<<ROWS, THREADS, smem_bytes>>>(pred, targ, pi, pep, out);
}